// round 11
// baseline (speedup 1.0000x reference)
#include <cuda_runtime.h>

#define B_   256
#define T_   250
#define NS   2048
#define H_   256
#define G3   768
#define NSEL 50
#define UBv  0.1f
#define RITER 32

// ---------------- scratch (device globals; no runtime alloc) ----------------
__device__ float g_xg[(size_t)T_ * B_ * G3];     // xg0, later reused as xg1
__device__ float g_hseq[(size_t)T_ * B_ * H_];   // hidden sequence (reused by layer 1)
__device__ float g_att[B_ * NS];
__device__ float g_log[B_ * NS];

__device__ __forceinline__ float sigmf(float x) { return 1.f / (1.f + expf(-x)); }

// packed fp32x2 helpers — identical numerics to two scalar rn-FMAs
__device__ __forceinline__ unsigned long long dupf(float x) {
    unsigned long long r;
    asm("mov.b64 %0, {%1, %1};" : "=l"(r) : "f"(x));
    return r;
}
#define FFMA2(d, a, b) asm("fma.rn.f32x2 %0, %1, %2, %0;" : "+l"(d) : "l"(a), "l"(b))
__device__ __forceinline__ void unpack2(unsigned long long v, float& lo, float& hi) {
    asm("mov.b64 {%0, %1}, %2;" : "=f"(lo), "=f"(hi) : "l"(v));
}
__device__ __forceinline__ unsigned smem_u32(const void* p) {
    return (unsigned)__cvta_generic_to_shared(p);
}
#define CLUSTER_SYNC() do { \
    asm volatile("barrier.cluster.arrive.aligned;" ::: "memory"); \
    asm volatile("barrier.cluster.wait.aligned;" ::: "memory"); \
} while (0)

// ============================================================================
// fp32 GEMM (FFMA2):  C[M,N] = act( A'[M,K] @ W[N,K]^T + bias[N] )   [as R6]
// ============================================================================
#define BM 128
#define BN 128
#define BK 16
#define ASTR 132
#define WSTR 140
__device__ __forceinline__ int wphys(int c) { return c + ((c >> 5) << 2); }

__device__ __forceinline__ void gemm_tile_compute(
    const float* __restrict__ As, const float* __restrict__ Ws,
    unsigned long long acc2[4][8], int tm, int wcol)
{
#pragma unroll
    for (int k = 0; k < BK; ++k) {
        ulonglong2 a01 = *(const ulonglong2*)&As[k * ASTR + tm * 8];
        ulonglong2 a23 = *(const ulonglong2*)&As[k * ASTR + tm * 8 + 4];
        float4 w0 = *(const float4*)&Ws[k * WSTR + wcol];
        float4 w1 = *(const float4*)&Ws[k * WSTR + wcol + 4];
        unsigned long long wd[8];
        wd[0] = dupf(w0.x); wd[1] = dupf(w0.y); wd[2] = dupf(w0.z); wd[3] = dupf(w0.w);
        wd[4] = dupf(w1.x); wd[5] = dupf(w1.y); wd[6] = dupf(w1.z); wd[7] = dupf(w1.w);
#pragma unroll
        for (int j = 0; j < 8; ++j) {
            FFMA2(acc2[0][j], a01.x, wd[j]);
            FFMA2(acc2[1][j], a01.y, wd[j]);
            FFMA2(acc2[2][j], a23.x, wd[j]);
            FFMA2(acc2[3][j], a23.y, wd[j]);
        }
    }
}

__global__ void __launch_bounds__(256, 2) gemm_kernel(
    const float* __restrict__ A, const float* __restrict__ W,
    const float* __restrict__ bias, float* __restrict__ C,
    int M, int N, int K, int permute, int act)
{
    __shared__ float As[2][BK * ASTR];
    __shared__ float Ws[2][BK * WSTR];
    const int tid = threadIdx.x;
    const int m0 = blockIdx.y * BM;
    const int n0 = blockIdx.x * BN;

    const int lr = tid >> 2;
    const int lk = (tid & 3) << 2;

    const int mrow0 = m0 + lr;
    const int mrow1 = m0 + lr + 64;
    const long long arow0 = permute ? ((long long)(mrow0 & 255) * T_ + (mrow0 >> 8)) : (long long)mrow0;
    const long long arow1 = permute ? ((long long)(mrow1 & 255) * T_ + (mrow1 >> 8)) : (long long)mrow1;
    const float* pa0 = A + arow0 * K + lk;
    const float* pa1 = A + arow1 * K + lk;
    const float* pw0 = W + (long long)(n0 + lr) * K + lk;
    const float* pw1 = W + (long long)(n0 + lr + 64) * K + lk;

    const int tm = tid >> 4;
    const int tn = tid & 15;
    const int wcol = tn * 8 + ((tn >> 2) << 2);
    const int wc0 = wphys(lr);
    const int wc1 = wphys(lr + 64);

    unsigned long long acc2[4][8];
#pragma unroll
    for (int i = 0; i < 4; ++i)
#pragma unroll
        for (int j = 0; j < 8; ++j) acc2[i][j] = 0ULL;

    {   // chunk 0
        float4 a0 = *(const float4*)pa0;
        float4 a1 = *(const float4*)pa1;
        float4 w0 = *(const float4*)pw0;
        float4 w1 = *(const float4*)pw1;
        float av0[4] = {a0.x, a0.y, a0.z, a0.w};
        float av1[4] = {a1.x, a1.y, a1.z, a1.w};
        float wv0[4] = {w0.x, w0.y, w0.z, w0.w};
        float wv1[4] = {w1.x, w1.y, w1.z, w1.w};
#pragma unroll
        for (int j = 0; j < 4; ++j) {
            As[0][(lk + j) * ASTR + lr]      = av0[j];
            As[0][(lk + j) * ASTR + lr + 64] = av1[j];
            Ws[0][(lk + j) * WSTR + wc0]     = wv0[j];
            Ws[0][(lk + j) * WSTR + wc1]     = wv1[j];
        }
    }
    __syncthreads();

    const int nCh = K / BK;
    for (int c = 1; c < nCh; ++c) {
        const int off = c * BK;
        float4 na0 = *(const float4*)(pa0 + off);
        float4 na1 = *(const float4*)(pa1 + off);
        float4 nw0 = *(const float4*)(pw0 + off);
        float4 nw1 = *(const float4*)(pw1 + off);

        gemm_tile_compute(As[(c - 1) & 1], Ws[(c - 1) & 1], acc2, tm, wcol);

        const int wb = c & 1;
        float av0[4] = {na0.x, na0.y, na0.z, na0.w};
        float av1[4] = {na1.x, na1.y, na1.z, na1.w};
        float wv0[4] = {nw0.x, nw0.y, nw0.z, nw0.w};
        float wv1[4] = {nw1.x, nw1.y, nw1.z, nw1.w};
#pragma unroll
        for (int j = 0; j < 4; ++j) {
            As[wb][(lk + j) * ASTR + lr]      = av0[j];
            As[wb][(lk + j) * ASTR + lr + 64] = av1[j];
            Ws[wb][(lk + j) * WSTR + wc0]     = wv0[j];
            Ws[wb][(lk + j) * WSTR + wc1]     = wv1[j];
        }
        __syncthreads();
    }
    gemm_tile_compute(As[(nCh - 1) & 1], Ws[(nCh - 1) & 1], acc2, tm, wcol);

#pragma unroll
    for (int p = 0; p < 4; ++p) {
        float rowlo[8], rowhi[8];
#pragma unroll
        for (int j = 0; j < 8; ++j) {
            float lo, hi; unpack2(acc2[p][j], lo, hi);
            float bj = bias[n0 + tn * 8 + j];
            lo += bj; hi += bj;
            if (act == 1)      { lo = sigmf(lo); hi = sigmf(hi); }
            else if (act == 2) { lo = lo * sigmf(lo); hi = hi * sigmf(hi); }
            rowlo[j] = lo; rowhi[j] = hi;
        }
        const long long mA = m0 + tm * 8 + 2 * p;
        float* c0 = &C[mA * N + n0 + tn * 8];
        float* c1 = &C[(mA + 1) * N + n0 + tn * 8];
        *(float4*)c0       = make_float4(rowlo[0], rowlo[1], rowlo[2], rowlo[3]);
        *(float4*)(c0 + 4) = make_float4(rowlo[4], rowlo[5], rowlo[6], rowlo[7]);
        *(float4*)c1       = make_float4(rowhi[0], rowhi[1], rowhi[2], rowhi[3]);
        *(float4*)(c1 + 4) = make_float4(rowhi[4], rowhi[5], rowhi[6], rowhi[7]);
    }
}

// ============================================================================
// Persistent GRU scan v4b — 8-CTA cluster per batch group, DSMEM h-exchange.
// Fix vs v4: NO peer push on the final step (peers may have exited; remote
// stores into an exited CTA's SMEM fault). All earlier pushes are drained by
// the end-of-step cluster barrier before any CTA can exit.
// ============================================================================
#define SC_W2_BYTES (3 * 128 * 32 * 16)     // 196608
#define SC_A2_BYTES (128 * 8 * 16)          // 16384 per buffer
#define SC_SMEM     (SC_W2_BYTES + 2 * SC_A2_BYTES)   // 229376

__global__ void __launch_bounds__(256, 1) __cluster_dims__(8, 1, 1)
gru_scan_kernel(const float* __restrict__ Whh, const float* __restrict__ bhh,
                const float* __restrict__ xg, float* __restrict__ hseq,
                int write_seq)
{
    extern __shared__ char smraw[];
    ulonglong2* W2 = (ulonglong2*)smraw;            // [(gate*128+k2)*32 + hcol]
    char* Abase = smraw + SC_W2_BYTES;              // 2 x [k2*8+p] ulonglong2

    const int tid = threadIdx.x;
    unsigned rank;
    asm("mov.u32 %0, %%cluster_ctarank;" : "=r"(rank));
    const int b0 = (blockIdx.x >> 3) * 16;
    const int h0 = (int)rank * 32;
    const int warp = tid >> 5, l = tid & 31;
    const int p    = l & 7;                  // row pair
    const int hcol = warp * 4 + (l >> 3);    // 0..31
    const int hg   = h0 + hcol;

    // one-time weight load: dup + pack k-pairs
    for (int idx = tid; idx < 96 * 64; idx += 256) {
        const int row = idx >> 6;            // gate*32 + hcol
        const int k4  = (idx & 63) << 2;
        const int gate = row >> 5, hc = row & 31;
        float4 wv = *(const float4*)(Whh + (size_t)(gate * H_ + h0 + hc) * H_ + k4);
        float w[4] = {wv.x, wv.y, wv.z, wv.w};
#pragma unroll
        for (int j = 0; j < 4; j += 2) {
            ulonglong2 u;
            u.x = dupf(w[j]); u.y = dupf(w[j + 1]);
            W2[(gate * 128 + ((k4 + j) >> 1)) * 32 + hc] = u;
        }
    }
    __syncthreads();

    const float br = bhh[hg], bz = bhh[H_ + hg], bn = bhh[2 * H_ + hg];
    // byte offset of (hg, rows 2p..2p+1) pair inside an A buffer
    const unsigned hoff = (unsigned)((((hg >> 1) * 8 + p) << 4) + ((hg & 1) << 3));
    const unsigned aSm = smem_u32(Abase);

    float xv[6];
    {   // prefetch xg for t=0
        const float* x0 = xg + (size_t)(b0 + 2 * p) * G3;
        const float* x1 = x0 + G3;
        xv[0] = x0[hg]; xv[1] = x0[H_ + hg]; xv[2] = x0[2 * H_ + hg];
        xv[3] = x1[hg]; xv[4] = x1[H_ + hg]; xv[5] = x1[2 * H_ + hg];
    }

    CLUSTER_SYNC();   // all CTAs resident & smem ready before first DSMEM push

    for (int t = 0; t < T_; ++t) {
        unsigned long long aR = 0ULL, aZ = 0ULL, aN = 0ULL;
        float hold0 = 0.f, hold1 = 0.f;

        if (t > 0) {
            const char* Ab = Abase + (t & 1) * SC_A2_BYTES;   // holds h(t-1)
            const ulonglong2* Ap = (const ulonglong2*)Ab + p;
            const ulonglong2* wR = W2 + hcol;
            const ulonglong2* wZ = W2 + 128 * 32 + hcol;
            const ulonglong2* wN = W2 + 256 * 32 + hcol;
#pragma unroll 8
            for (int k2 = 0; k2 < 128; ++k2) {
                ulonglong2 av = Ap[k2 * 8];
                ulonglong2 r2 = wR[k2 * 32];
                ulonglong2 z2 = wZ[k2 * 32];
                ulonglong2 n2 = wN[k2 * 32];
                FFMA2(aR, av.x, r2.x); FFMA2(aR, av.y, r2.y);
                FFMA2(aZ, av.x, z2.x); FFMA2(aZ, av.y, z2.y);
                FFMA2(aN, av.x, n2.x); FFMA2(aN, av.y, n2.y);
            }
            const float2 hv = *(const float2*)(Ab + hoff);
            hold0 = hv.x; hold1 = hv.y;
        }

        float r0v, r1v, z0v, z1v, n0v, n1v;
        unpack2(aR, r0v, r1v); unpack2(aZ, z0v, z1v); unpack2(aN, n0v, n1v);

        const float rA = sigmf(xv[0] + r0v + br);
        const float zA = sigmf(xv[1] + z0v + bz);
        const float nA = tanhf(xv[2] + rA * (n0v + bn));
        const float hA = (1.f - zA) * nA + zA * hold0;
        const float rB = sigmf(xv[3] + r1v + br);
        const float zB = sigmf(xv[4] + z1v + bz);
        const float nB = tanhf(xv[5] + rB * (n1v + bn));
        const float hB = (1.f - zB) * nB + zB * hold1;

        if (t < T_ - 1) {
            // push packed h pair into ALL 8 CTAs' next buffer (incl. self).
            // Safe: the end-of-step cluster barrier below drains these before
            // any CTA can advance (and the last step never pushes).
            unsigned long long hpack;
            asm("mov.b64 %0, {%1, %2};" : "=l"(hpack) : "f"(hA), "f"(hB));
            const unsigned dst = aSm + (unsigned)(((t + 1) & 1) * SC_A2_BYTES) + hoff;
#pragma unroll
            for (int rk = 0; rk < 8; ++rk) {
                unsigned ra;
                asm volatile("mapa.shared::cluster.u32 %0, %1, %2;"
                             : "=r"(ra) : "r"(dst), "r"(rk));
                asm volatile("st.shared::cluster.u64 [%0], %1;"
                             :: "r"(ra), "l"(hpack) : "memory");
            }
        }

        if (write_seq || t == T_ - 1) {
            float* hout = hseq + (size_t)t * (B_ * H_);
            hout[(size_t)(b0 + 2 * p) * H_ + hg]     = hA;
            hout[(size_t)(b0 + 2 * p + 1) * H_ + hg] = hB;
        }

        if (t < T_ - 1) {
            // prefetch xg(t+1) before the barrier (no cross-CTA dependency)
            const float* x0 = xg + ((size_t)(t + 1) * B_ + b0 + 2 * p) * G3;
            const float* x1 = x0 + G3;
            xv[0] = x0[hg]; xv[1] = x0[H_ + hg]; xv[2] = x0[2 * H_ + hg];
            xv[3] = x1[hg]; xv[4] = x1[H_ + hg]; xv[5] = x1[2 * H_ + hg];

            CLUSTER_SYNC();   // drains DSMEM pushes; protects buffer swap
        }
    }
}

// ============================================================================
// Finalize per batch row: top-50 -> mask; softmax; mask+normalize; rebalance.
// ============================================================================
__global__ void __launch_bounds__(256) finalize_kernel(
    const float* __restrict__ att, const float* __restrict__ logits,
    float* __restrict__ out)
{
    __shared__ float a_s[NS];
    __shared__ float w_s[NS];
    __shared__ unsigned char m_s[NS];
    __shared__ float rf[256];
    __shared__ float rb[256];
    __shared__ int   ri[256];
    __shared__ float sc[8];

    const int b = blockIdx.x;
    const int tid = threadIdx.x;

    for (int n = tid; n < NS; n += 256) {
        a_s[n] = att[(long long)b * NS + n];
        w_s[n] = logits[(long long)b * NS + n];
        m_s[n] = 0;
    }
    if (tid == 0) sc[4] = 0.f;
    __syncthreads();

    for (int it = 0; it < NSEL; ++it) {
        float bv = -3.402823466e38f; int bi = 0x7fffffff;
        for (int n = tid; n < NS; n += 256) {
            float v = a_s[n];
            if (v > bv) { bv = v; bi = n; }
        }
        rf[tid] = bv; ri[tid] = bi;
        __syncthreads();
        for (int s = 128; s > 0; s >>= 1) {
            if (tid < s) {
                float v2 = rf[tid + s]; int i2 = ri[tid + s];
                if (v2 > rf[tid] || (v2 == rf[tid] && i2 < ri[tid])) { rf[tid] = v2; ri[tid] = i2; }
            }
            __syncthreads();
        }
        if (tid == 0) { m_s[ri[0]] = 1; a_s[ri[0]] = -3.402823466e38f; }
        __syncthreads();
    }

    float lm = -3.402823466e38f;
    for (int n = tid; n < NS; n += 256) lm = fmaxf(lm, w_s[n]);
    rf[tid] = lm; __syncthreads();
    for (int s = 128; s > 0; s >>= 1) { if (tid < s) rf[tid] = fmaxf(rf[tid], rf[tid + s]); __syncthreads(); }
    const float Mx = rf[0];
    __syncthreads();

    float ps = 0.f;
    for (int n = tid; n < NS; n += 256) { float e = expf(w_s[n] - Mx); w_s[n] = e; ps += e; }
    rf[tid] = ps; __syncthreads();
    for (int s = 128; s > 0; s >>= 1) { if (tid < s) rf[tid] += rf[tid + s]; __syncthreads(); }
    const float S = rf[0];
    __syncthreads();

    float pm = 0.f;
    for (int n = tid; n < NS; n += 256) {
        float mw = m_s[n] ? (w_s[n] / S) : 0.f;
        w_s[n] = mw; pm += mw;
    }
    rf[tid] = pm; __syncthreads();
    for (int s = 128; s > 0; s >>= 1) { if (tid < s) rf[tid] += rf[tid + s]; __syncthreads(); }
    const float SM = rf[0];
    __syncthreads();

    for (int n = tid; n < NS; n += 256) {
        float w0 = w_s[n] / (SM + 1e-8f);
        a_s[n] = w0;
        w_s[n] = fminf(fmaxf(w0, 0.f), UBv);
    }
    __syncthreads();

    for (int it = 0; it < RITER; ++it) {
        float pl = 0.f, pn = 0.f; int ph = 0;
        for (int n = tid; n < NS; n += 256) {
            float w = w_s[n];
            int nm = (w != UBv) && m_s[n];
            pl += a_s[n] - w;
            if (nm) { pn += w; ph = 1; }
        }
        rf[tid] = pl; rb[tid] = pn; ri[tid] = ph;
        __syncthreads();
        for (int s = 128; s > 0; s >>= 1) {
            if (tid < s) { rf[tid] += rf[tid + s]; rb[tid] += rb[tid + s]; ri[tid] |= ri[tid + s]; }
            __syncthreads();
        }
        if (tid == 0) { sc[0] = rf[0]; sc[1] = rb[0]; sc[2] = ri[0] ? 1.f : 0.f; }
        __syncthreads();

        const float leftover = sc[0];
        const float nsum = sc[1];
        const bool hasnom = (sc[2] != 0.f);
        const bool done = (sc[4] != 0.f);
        const bool upd = (!done) && hasnom;
        const float denom = (nsum == 0.f) ? 1.f : nsum;

        int po = 0;
        for (int n = tid; n < NS; n += 256) {
            float w = w_s[n];
            int nm = (w != UBv) && m_s[n];
            float gift = (leftover * (nm ? w : 0.f)) / denom;
            float w1 = upd ? (w + gift) : w;
            if (w1 > UBv) po = 1;
            w_s[n] = w1;
            if (upd) a_s[n] = w1;
        }
        ri[tid] = po;
        __syncthreads();
        for (int s = 128; s > 0; s >>= 1) { if (tid < s) ri[tid] |= ri[tid + s]; __syncthreads(); }
        const bool over = (ri[0] != 0);
        __syncthreads();

        if (upd && over)
            for (int n = tid; n < NS; n += 256)
                w_s[n] = fminf(fmaxf(w_s[n], 0.f), UBv);
        if (tid == 0) {
            bool d = done || ((!done) && (!hasnom)) || (upd && (!over));
            sc[4] = d ? 1.f : 0.f;
        }
        __syncthreads();
    }

    for (int n = tid; n < NS; n += 256)
        out[(long long)b * NS + n] = w_s[n];
}

// ============================================================================
extern "C" void kernel_launch(void* const* d_in, const int* in_sizes, int n_in,
                              void* d_out, int out_size)
{
    (void)in_sizes; (void)n_in; (void)out_size;
    const float* x    = (const float*)d_in[0];
    const float* Wih0 = (const float*)d_in[1];
    const float* Whh0 = (const float*)d_in[2];
    const float* bih0 = (const float*)d_in[3];
    const float* bhh0 = (const float*)d_in[4];
    const float* Wih1 = (const float*)d_in[5];
    const float* Whh1 = (const float*)d_in[6];
    const float* bih1 = (const float*)d_in[7];
    const float* bhh1 = (const float*)d_in[8];
    const float* Wa   = (const float*)d_in[9];
    const float* ba   = (const float*)d_in[10];
    const float* Wf   = (const float*)d_in[11];
    const float* bf   = (const float*)d_in[12];
    float* out = (float*)d_out;

    float *xg, *hseq, *attb, *logb;
    cudaGetSymbolAddress((void**)&xg,   g_xg);
    cudaGetSymbolAddress((void**)&hseq, g_hseq);
    cudaGetSymbolAddress((void**)&attb, g_att);
    cudaGetSymbolAddress((void**)&logb, g_log);

    cudaFuncSetAttribute(gru_scan_kernel,
                         cudaFuncAttributeMaxDynamicSharedMemorySize, SC_SMEM);

    const int M = T_ * B_;   // 64000

    // xg0 = permute(x) @ Wih0^T + bih0     [T*B, 768]
    gemm_kernel<<<dim3(G3 / BN, M / BM), 256>>>(x, Wih0, bih0, xg, M, G3, NS, 1, 0);

    // GRU layer 0 (cluster-persistent): writes full hidden sequence
    gru_scan_kernel<<<128, 256, SC_SMEM>>>(Whh0, bhh0, xg, hseq, 1);

    // xg1 = hseq @ Wih1^T + bih1   (reuse g_xg)
    gemm_kernel<<<dim3(G3 / BN, M / BM), 256>>>(hseq, Wih1, bih1, xg, M, G3, H_, 0, 0);

    // GRU layer 1 (cluster-persistent): writes only final h into hseq[T-1]
    gru_scan_kernel<<<128, 256, SC_SMEM>>>(Whh1, bhh1, xg, hseq, 0);

    const float* hT = hseq + (size_t)(T_ - 1) * B_ * H_;

    // att = sigmoid(hT @ Wa^T + ba);  logits = silu(hT @ Wf^T + bf)
    gemm_kernel<<<dim3(NS / BN, B_ / BM), 256>>>(hT, Wa, ba, attb, B_, NS, H_, 0, 1);
    gemm_kernel<<<dim3(NS / BN, B_ / BM), 256>>>(hT, Wf, bf, logb, B_, NS, H_, 0, 2);

    finalize_kernel<<<B_, 256>>>(attb, logb, out);
}

// round 12
// speedup vs baseline: 1.3458x; 1.3458x over previous
#include <cuda_runtime.h>

#define B_   256
#define T_   250
#define NS   2048
#define H_   256
#define G3   768
#define NSEL 50
#define UBv  0.1f
#define RITER 32

// ---------------- scratch (device globals; no runtime alloc) ----------------
__device__ float g_xg[(size_t)T_ * B_ * G3];     // xg0, later reused as xg1
__device__ float g_hseq[(size_t)T_ * B_ * H_];   // hidden sequence (reused by layer 1)
__device__ float g_att[B_ * NS];
__device__ float g_log[B_ * NS];
__device__ unsigned long long g_cntA[128];       // 8 group counters, 128B apart

__device__ __forceinline__ float sigmf(float x) { return 1.f / (1.f + expf(-x)); }

// packed fp32x2 helpers — identical numerics to two scalar rn-FMAs
__device__ __forceinline__ unsigned long long dupf(float x) {
    unsigned long long r;
    asm("mov.b64 %0, {%1, %1};" : "=l"(r) : "f"(x));
    return r;
}
#define FFMA2(d, a, b) asm("fma.rn.f32x2 %0, %1, %2, %0;" : "+l"(d) : "l"(a), "l"(b))
#define FADD2(d, a)    asm("add.rn.f32x2 %0, %0, %1;"     : "+l"(d) : "l"(a))
__device__ __forceinline__ void unpack2(unsigned long long v, float& lo, float& hi) {
    asm("mov.b64 {%0, %1}, %2;" : "=f"(lo), "=f"(hi) : "l"(v));
}

// ============================================================================
// fp32 GEMM (FFMA2):  C[M,N] = act( A'[M,K] @ W[N,K]^T + bias[N] )   [as R6]
// ============================================================================
#define BM 128
#define BN 128
#define BK 16
#define ASTR 132
#define WSTR 140
__device__ __forceinline__ int wphys(int c) { return c + ((c >> 5) << 2); }

__device__ __forceinline__ void gemm_tile_compute(
    const float* __restrict__ As, const float* __restrict__ Ws,
    unsigned long long acc2[4][8], int tm, int wcol)
{
#pragma unroll
    for (int k = 0; k < BK; ++k) {
        ulonglong2 a01 = *(const ulonglong2*)&As[k * ASTR + tm * 8];
        ulonglong2 a23 = *(const ulonglong2*)&As[k * ASTR + tm * 8 + 4];
        float4 w0 = *(const float4*)&Ws[k * WSTR + wcol];
        float4 w1 = *(const float4*)&Ws[k * WSTR + wcol + 4];
        unsigned long long wd[8];
        wd[0] = dupf(w0.x); wd[1] = dupf(w0.y); wd[2] = dupf(w0.z); wd[3] = dupf(w0.w);
        wd[4] = dupf(w1.x); wd[5] = dupf(w1.y); wd[6] = dupf(w1.z); wd[7] = dupf(w1.w);
#pragma unroll
        for (int j = 0; j < 8; ++j) {
            FFMA2(acc2[0][j], a01.x, wd[j]);
            FFMA2(acc2[1][j], a01.y, wd[j]);
            FFMA2(acc2[2][j], a23.x, wd[j]);
            FFMA2(acc2[3][j], a23.y, wd[j]);
        }
    }
}

__global__ void __launch_bounds__(256, 2) gemm_kernel(
    const float* __restrict__ A, const float* __restrict__ W,
    const float* __restrict__ bias, float* __restrict__ C,
    int M, int N, int K, int permute, int act)
{
    __shared__ float As[2][BK * ASTR];
    __shared__ float Ws[2][BK * WSTR];
    const int tid = threadIdx.x;
    const int m0 = blockIdx.y * BM;
    const int n0 = blockIdx.x * BN;

    const int lr = tid >> 2;
    const int lk = (tid & 3) << 2;

    const int mrow0 = m0 + lr;
    const int mrow1 = m0 + lr + 64;
    const long long arow0 = permute ? ((long long)(mrow0 & 255) * T_ + (mrow0 >> 8)) : (long long)mrow0;
    const long long arow1 = permute ? ((long long)(mrow1 & 255) * T_ + (mrow1 >> 8)) : (long long)mrow1;
    const float* pa0 = A + arow0 * K + lk;
    const float* pa1 = A + arow1 * K + lk;
    const float* pw0 = W + (long long)(n0 + lr) * K + lk;
    const float* pw1 = W + (long long)(n0 + lr + 64) * K + lk;

    const int tm = tid >> 4;
    const int tn = tid & 15;
    const int wcol = tn * 8 + ((tn >> 2) << 2);
    const int wc0 = wphys(lr);
    const int wc1 = wphys(lr + 64);

    unsigned long long acc2[4][8];
#pragma unroll
    for (int i = 0; i < 4; ++i)
#pragma unroll
        for (int j = 0; j < 8; ++j) acc2[i][j] = 0ULL;

    {   // chunk 0
        float4 a0 = *(const float4*)pa0;
        float4 a1 = *(const float4*)pa1;
        float4 w0 = *(const float4*)pw0;
        float4 w1 = *(const float4*)pw1;
        float av0[4] = {a0.x, a0.y, a0.z, a0.w};
        float av1[4] = {a1.x, a1.y, a1.z, a1.w};
        float wv0[4] = {w0.x, w0.y, w0.z, w0.w};
        float wv1[4] = {w1.x, w1.y, w1.z, w1.w};
#pragma unroll
        for (int j = 0; j < 4; ++j) {
            As[0][(lk + j) * ASTR + lr]      = av0[j];
            As[0][(lk + j) * ASTR + lr + 64] = av1[j];
            Ws[0][(lk + j) * WSTR + wc0]     = wv0[j];
            Ws[0][(lk + j) * WSTR + wc1]     = wv1[j];
        }
    }
    __syncthreads();

    const int nCh = K / BK;
    for (int c = 1; c < nCh; ++c) {
        const int off = c * BK;
        float4 na0 = *(const float4*)(pa0 + off);
        float4 na1 = *(const float4*)(pa1 + off);
        float4 nw0 = *(const float4*)(pw0 + off);
        float4 nw1 = *(const float4*)(pw1 + off);

        gemm_tile_compute(As[(c - 1) & 1], Ws[(c - 1) & 1], acc2, tm, wcol);

        const int wb = c & 1;
        float av0[4] = {na0.x, na0.y, na0.z, na0.w};
        float av1[4] = {na1.x, na1.y, na1.z, na1.w};
        float wv0[4] = {nw0.x, nw0.y, nw0.z, nw0.w};
        float wv1[4] = {nw1.x, nw1.y, nw1.z, nw1.w};
#pragma unroll
        for (int j = 0; j < 4; ++j) {
            As[wb][(lk + j) * ASTR + lr]      = av0[j];
            As[wb][(lk + j) * ASTR + lr + 64] = av1[j];
            Ws[wb][(lk + j) * WSTR + wc0]     = wv0[j];
            Ws[wb][(lk + j) * WSTR + wc1]     = wv1[j];
        }
        __syncthreads();
    }
    gemm_tile_compute(As[(nCh - 1) & 1], Ws[(nCh - 1) & 1], acc2, tm, wcol);

#pragma unroll
    for (int p = 0; p < 4; ++p) {
        float rowlo[8], rowhi[8];
#pragma unroll
        for (int j = 0; j < 8; ++j) {
            float lo, hi; unpack2(acc2[p][j], lo, hi);
            float bj = bias[n0 + tn * 8 + j];
            lo += bj; hi += bj;
            if (act == 1)      { lo = sigmf(lo); hi = sigmf(hi); }
            else if (act == 2) { lo = lo * sigmf(lo); hi = hi * sigmf(hi); }
            rowlo[j] = lo; rowhi[j] = hi;
        }
        const long long mA = m0 + tm * 8 + 2 * p;
        float* c0 = &C[mA * N + n0 + tn * 8];
        float* c1 = &C[(mA + 1) * N + n0 + tn * 8];
        *(float4*)c0       = make_float4(rowlo[0], rowlo[1], rowlo[2], rowlo[3]);
        *(float4*)(c0 + 4) = make_float4(rowlo[4], rowlo[5], rowlo[6], rowlo[7]);
        *(float4*)c1       = make_float4(rowhi[0], rowhi[1], rowhi[2], rowhi[3]);
        *(float4*)(c1 + 4) = make_float4(rowhi[4], rowhi[5], rowhi[6], rowhi[7]);
    }
}

// ============================================================================
// Persistent GRU scan — EXACT R6 design; ONLY change: per-batch-group barrier
// counters (8 counters, 128B apart, 16 arrivals each) instead of one global.
// Grid 128 blocks = 8 batch-tiles(32) x 16 hcol-tiles(16); 256 threads/block.
// ============================================================================
#define GRU_W2_ULL   (3 * 256 * 16)
#define GRU_HT_F     (256 * 36)
#define GRU_PART_ULL (3 * 64 * 12)
#define GRU_SMEM     (GRU_W2_ULL * 8 + GRU_HT_F * 4 + GRU_PART_ULL * 8)

__global__ void __launch_bounds__(256, 1) gru_scan_kernel(
    const float* __restrict__ Whh, const float* __restrict__ bhh,
    const float* __restrict__ xg, float* __restrict__ hseq)
{
    extern __shared__ char smraw[];
    unsigned long long* w2  = (unsigned long long*)smraw;
    float*              hT  = (float*)(smraw + GRU_W2_ULL * 8);
    unsigned long long* prt = (unsigned long long*)(smraw + GRU_W2_ULL * 8 + GRU_HT_F * 4);

    const int tid = threadIdx.x;
    const int bg = blockIdx.x >> 4;           // batch group 0..7
    const int b0 = bg * 32;
    const int h0 = (blockIdx.x & 15) * 16;
    const int c  = tid & 15;
    const int g  = (tid >> 4) & 3;
    const int ks = tid >> 6;
    const int r0 = g * 8;
    const int slot = (g << 4) | c;

    for (int idx = tid; idx < 48 * 64; idx += 256) {
        const int row = idx >> 6;
        const int k4  = (idx & 63) << 2;
        const int gate = row >> 4, cc = row & 15;
        float4 wv = *(const float4*)(Whh + (size_t)(gate * H_ + h0 + cc) * H_ + k4);
        w2[(gate * 256 + k4 + 0) * 16 + cc] = dupf(wv.x);
        w2[(gate * 256 + k4 + 1) * 16 + cc] = dupf(wv.y);
        w2[(gate * 256 + k4 + 2) * 16 + cc] = dupf(wv.z);
        w2[(gate * 256 + k4 + 3) * 16 + cc] = dupf(wv.w);
    }
    __syncthreads();

    const int hg = h0 + c;
    const float br = bhh[hg], bz = bhh[H_ + hg], bn = bhh[2 * H_ + hg];
    const int lr  = tid & 31;
    const int lk0 = (tid >> 5) * 32;

    unsigned long long* grp = &g_cntA[bg * 16];   // 128B-spaced counter

    for (int t = 0; t < T_; ++t) {
        unsigned long long aR[4] = {0, 0, 0, 0}, aZ[4] = {0, 0, 0, 0}, aN[4] = {0, 0, 0, 0};
        float xv[3][8];

        if (ks == 0) {
            const float* xrow = xg + (size_t)t * (B_ * G3);
#pragma unroll
            for (int i = 0; i < 8; ++i) {
                const float* xr = xrow + (size_t)(b0 + r0 + i) * G3;
                xv[0][i] = xr[hg];
                xv[1][i] = xr[H_ + hg];
                xv[2][i] = xr[2 * H_ + hg];
            }
        }

        if (t > 0) {
            const float* src = hseq + (size_t)(t - 1) * (B_ * H_)
                                    + (size_t)(b0 + lr) * H_ + lk0;
#pragma unroll
            for (int q = 0; q < 8; ++q) {
                float4 v = __ldcg((const float4*)(src + q * 4));
                const int k = lk0 + q * 4;
                hT[(k + 0) * 36 + lr] = v.x;
                hT[(k + 1) * 36 + lr] = v.y;
                hT[(k + 2) * 36 + lr] = v.z;
                hT[(k + 3) * 36 + lr] = v.w;
            }
            __syncthreads();

            const int kb = ks * 64;
#pragma unroll 4
            for (int kk = 0; kk < 64; ++kk) {
                const int k = kb + kk;
                ulonglong2 a01 = *(const ulonglong2*)&hT[k * 36 + r0];
                ulonglong2 a23 = *(const ulonglong2*)&hT[k * 36 + r0 + 4];
                unsigned long long wr = w2[k * 16 + c];
                unsigned long long wz = w2[(256 + k) * 16 + c];
                unsigned long long wn = w2[(512 + k) * 16 + c];
                FFMA2(aR[0], a01.x, wr); FFMA2(aR[1], a01.y, wr);
                FFMA2(aR[2], a23.x, wr); FFMA2(aR[3], a23.y, wr);
                FFMA2(aZ[0], a01.x, wz); FFMA2(aZ[1], a01.y, wz);
                FFMA2(aZ[2], a23.x, wz); FFMA2(aZ[3], a23.y, wz);
                FFMA2(aN[0], a01.x, wn); FFMA2(aN[1], a01.y, wn);
                FFMA2(aN[2], a23.x, wn); FFMA2(aN[3], a23.y, wn);
            }

            if (ks != 0) {
                unsigned long long* p = prt + ((ks - 1) * 64 + slot) * 12;
#pragma unroll
                for (int i = 0; i < 4; ++i) { p[i] = aR[i]; p[4 + i] = aZ[i]; p[8 + i] = aN[i]; }
            }
            __syncthreads();
            if (ks == 0) {
#pragma unroll
                for (int q = 0; q < 3; ++q) {
                    const unsigned long long* p = prt + (q * 64 + slot) * 12;
#pragma unroll
                    for (int i = 0; i < 4; ++i) {
                        FADD2(aR[i], p[i]); FADD2(aZ[i], p[4 + i]); FADD2(aN[i], p[8 + i]);
                    }
                }
            }
        }

        if (ks == 0) {
            float rr[8], zz[8], nn[8], hold[8];
#pragma unroll
            for (int i = 0; i < 4; ++i) {
                unpack2(aR[i], rr[2 * i], rr[2 * i + 1]);
                unpack2(aZ[i], zz[2 * i], zz[2 * i + 1]);
                unpack2(aN[i], nn[2 * i], nn[2 * i + 1]);
            }
#pragma unroll
            for (int i = 0; i < 8; ++i)
                hold[i] = (t > 0) ? hT[hg * 36 + r0 + i] : 0.f;

            float* hout = hseq + (size_t)t * (B_ * H_);
#pragma unroll
            for (int i = 0; i < 8; ++i) {
                const float r = sigmf(xv[0][i] + rr[i] + br);
                const float z = sigmf(xv[1][i] + zz[i] + bz);
                const float n = tanhf(xv[2][i] + r * (nn[i] + bn));
                hout[(size_t)(b0 + r0 + i) * H_ + hg] = (1.f - z) * n + z * hold[i];
            }
        }

        if (t < T_ - 1) {
            __threadfence();
            __syncthreads();
            if (tid == 0) {
                atomicAdd(grp, 1ULL);
                const unsigned long long target =
                    (unsigned long long)(t + 1) * 16ULL;   // 16 blocks per group
                volatile unsigned long long* p = (volatile unsigned long long*)grp;
                while (*p < target) { }
                __threadfence();
            }
            __syncthreads();
        }
    }
}

__global__ void reset_sync_kernel() {
    if (threadIdx.x < 128) g_cntA[threadIdx.x] = 0ULL;
}

// ============================================================================
// Finalize per batch row: top-50 -> mask; softmax; mask+normalize; rebalance.
// ============================================================================
__global__ void __launch_bounds__(256) finalize_kernel(
    const float* __restrict__ att, const float* __restrict__ logits,
    float* __restrict__ out)
{
    __shared__ float a_s[NS];
    __shared__ float w_s[NS];
    __shared__ unsigned char m_s[NS];
    __shared__ float rf[256];
    __shared__ float rb[256];
    __shared__ int   ri[256];
    __shared__ float sc[8];

    const int b = blockIdx.x;
    const int tid = threadIdx.x;

    for (int n = tid; n < NS; n += 256) {
        a_s[n] = att[(long long)b * NS + n];
        w_s[n] = logits[(long long)b * NS + n];
        m_s[n] = 0;
    }
    if (tid == 0) sc[4] = 0.f;
    __syncthreads();

    for (int it = 0; it < NSEL; ++it) {
        float bv = -3.402823466e38f; int bi = 0x7fffffff;
        for (int n = tid; n < NS; n += 256) {
            float v = a_s[n];
            if (v > bv) { bv = v; bi = n; }
        }
        rf[tid] = bv; ri[tid] = bi;
        __syncthreads();
        for (int s = 128; s > 0; s >>= 1) {
            if (tid < s) {
                float v2 = rf[tid + s]; int i2 = ri[tid + s];
                if (v2 > rf[tid] || (v2 == rf[tid] && i2 < ri[tid])) { rf[tid] = v2; ri[tid] = i2; }
            }
            __syncthreads();
        }
        if (tid == 0) { m_s[ri[0]] = 1; a_s[ri[0]] = -3.402823466e38f; }
        __syncthreads();
    }

    float lm = -3.402823466e38f;
    for (int n = tid; n < NS; n += 256) lm = fmaxf(lm, w_s[n]);
    rf[tid] = lm; __syncthreads();
    for (int s = 128; s > 0; s >>= 1) { if (tid < s) rf[tid] = fmaxf(rf[tid], rf[tid + s]); __syncthreads(); }
    const float Mx = rf[0];
    __syncthreads();

    float ps = 0.f;
    for (int n = tid; n < NS; n += 256) { float e = expf(w_s[n] - Mx); w_s[n] = e; ps += e; }
    rf[tid] = ps; __syncthreads();
    for (int s = 128; s > 0; s >>= 1) { if (tid < s) rf[tid] += rf[tid + s]; __syncthreads(); }
    const float S = rf[0];
    __syncthreads();

    float pm = 0.f;
    for (int n = tid; n < NS; n += 256) {
        float mw = m_s[n] ? (w_s[n] / S) : 0.f;
        w_s[n] = mw; pm += mw;
    }
    rf[tid] = pm; __syncthreads();
    for (int s = 128; s > 0; s >>= 1) { if (tid < s) rf[tid] += rf[tid + s]; __syncthreads(); }
    const float SM = rf[0];
    __syncthreads();

    for (int n = tid; n < NS; n += 256) {
        float w0 = w_s[n] / (SM + 1e-8f);
        a_s[n] = w0;
        w_s[n] = fminf(fmaxf(w0, 0.f), UBv);
    }
    __syncthreads();

    for (int it = 0; it < RITER; ++it) {
        float pl = 0.f, pn = 0.f; int ph = 0;
        for (int n = tid; n < NS; n += 256) {
            float w = w_s[n];
            int nm = (w != UBv) && m_s[n];
            pl += a_s[n] - w;
            if (nm) { pn += w; ph = 1; }
        }
        rf[tid] = pl; rb[tid] = pn; ri[tid] = ph;
        __syncthreads();
        for (int s = 128; s > 0; s >>= 1) {
            if (tid < s) { rf[tid] += rf[tid + s]; rb[tid] += rb[tid + s]; ri[tid] |= ri[tid + s]; }
            __syncthreads();
        }
        if (tid == 0) { sc[0] = rf[0]; sc[1] = rb[0]; sc[2] = ri[0] ? 1.f : 0.f; }
        __syncthreads();

        const float leftover = sc[0];
        const float nsum = sc[1];
        const bool hasnom = (sc[2] != 0.f);
        const bool done = (sc[4] != 0.f);
        const bool upd = (!done) && hasnom;
        const float denom = (nsum == 0.f) ? 1.f : nsum;

        int po = 0;
        for (int n = tid; n < NS; n += 256) {
            float w = w_s[n];
            int nm = (w != UBv) && m_s[n];
            float gift = (leftover * (nm ? w : 0.f)) / denom;
            float w1 = upd ? (w + gift) : w;
            if (w1 > UBv) po = 1;
            w_s[n] = w1;
            if (upd) a_s[n] = w1;
        }
        ri[tid] = po;
        __syncthreads();
        for (int s = 128; s > 0; s >>= 1) { if (tid < s) ri[tid] |= ri[tid + s]; __syncthreads(); }
        const bool over = (ri[0] != 0);
        __syncthreads();

        if (upd && over)
            for (int n = tid; n < NS; n += 256)
                w_s[n] = fminf(fmaxf(w_s[n], 0.f), UBv);
        if (tid == 0) {
            bool d = done || ((!done) && (!hasnom)) || (upd && (!over));
            sc[4] = d ? 1.f : 0.f;
        }
        __syncthreads();
    }

    for (int n = tid; n < NS; n += 256)
        out[(long long)b * NS + n] = w_s[n];
}

// ============================================================================
extern "C" void kernel_launch(void* const* d_in, const int* in_sizes, int n_in,
                              void* d_out, int out_size)
{
    (void)in_sizes; (void)n_in; (void)out_size;
    const float* x    = (const float*)d_in[0];
    const float* Wih0 = (const float*)d_in[1];
    const float* Whh0 = (const float*)d_in[2];
    const float* bih0 = (const float*)d_in[3];
    const float* bhh0 = (const float*)d_in[4];
    const float* Wih1 = (const float*)d_in[5];
    const float* Whh1 = (const float*)d_in[6];
    const float* bih1 = (const float*)d_in[7];
    const float* bhh1 = (const float*)d_in[8];
    const float* Wa   = (const float*)d_in[9];
    const float* ba   = (const float*)d_in[10];
    const float* Wf   = (const float*)d_in[11];
    const float* bf   = (const float*)d_in[12];
    float* out = (float*)d_out;

    float *xg, *hseq, *attb, *logb;
    cudaGetSymbolAddress((void**)&xg,   g_xg);
    cudaGetSymbolAddress((void**)&hseq, g_hseq);
    cudaGetSymbolAddress((void**)&attb, g_att);
    cudaGetSymbolAddress((void**)&logb, g_log);

    cudaFuncSetAttribute(gru_scan_kernel,
                         cudaFuncAttributeMaxDynamicSharedMemorySize, GRU_SMEM);

    const int M = T_ * B_;   // 64000

    // xg0 = permute(x) @ Wih0^T + bih0     [T*B, 768]
    gemm_kernel<<<dim3(G3 / BN, M / BM), 256>>>(x, Wih0, bih0, xg, M, G3, NS, 1, 0);

    // GRU layer 0 (persistent, per-group atomic barrier)
    reset_sync_kernel<<<1, 128>>>();
    gru_scan_kernel<<<128, 256, GRU_SMEM>>>(Whh0, bhh0, xg, hseq);

    // xg1 = hseq @ Wih1^T + bih1   (reuse g_xg)
    gemm_kernel<<<dim3(G3 / BN, M / BM), 256>>>(hseq, Wih1, bih1, xg, M, G3, H_, 0, 0);

    // GRU layer 1 (persistent): reuses hseq as its own sequence scratch
    reset_sync_kernel<<<1, 128>>>();
    gru_scan_kernel<<<128, 256, GRU_SMEM>>>(Whh1, bhh1, xg, hseq);

    const float* hT = hseq + (size_t)(T_ - 1) * B_ * H_;

    // att = sigmoid(hT @ Wa^T + ba);  logits = silu(hT @ Wf^T + bf)
    gemm_kernel<<<dim3(NS / BN, B_ / BM), 256>>>(hT, Wa, ba, attb, B_, NS, H_, 0, 1);
    gemm_kernel<<<dim3(NS / BN, B_ / BM), 256>>>(hT, Wf, bf, logb, B_, NS, H_, 0, 2);

    finalize_kernel<<<B_, 256>>>(attb, logb, out);
}

// round 14
// speedup vs baseline: 1.8318x; 1.3611x over previous
#include <cuda_runtime.h>
#include <cuda_bf16.h>

#define B_   256
#define T_   250
#define NS   2048
#define H_   256
#define G3   768
#define NSEL 50
#define UBv  0.1f
#define RITER 32

// ---------------- scratch (device globals; no runtime alloc) ----------------
__device__ float g_xg[(size_t)T_ * B_ * G3];     // xg0, later reused as xg1
__device__ float g_hseq[(size_t)T_ * B_ * H_];   // hidden sequence (reused by layer 1)
__device__ float g_att[B_ * NS];
__device__ float g_log[B_ * NS];
__device__ unsigned long long g_cntA[128];       // 8 group counters, 128B apart

// bf16 2-split planes (A reused for x [64000x2048] then hseq [64000x256])
__device__ uint4 g_a0[16384000];                 // A hi
__device__ uint4 g_a1[16384000];                 // A lo
__device__ uint4 g_w0[196608];                   // W hi
__device__ uint4 g_w1[196608];                   // W lo

__device__ __forceinline__ float sigmf(float x) { return 1.f / (1.f + expf(-x)); }

// packed fp32x2 helpers — identical numerics to two scalar rn-FMAs
__device__ __forceinline__ unsigned long long dupf(float x) {
    unsigned long long r;
    asm("mov.b64 %0, {%1, %1};" : "=l"(r) : "f"(x));
    return r;
}
#define FFMA2(d, a, b) asm("fma.rn.f32x2 %0, %1, %2, %0;" : "+l"(d) : "l"(a), "l"(b))
#define FADD2(d, a)    asm("add.rn.f32x2 %0, %0, %1;"     : "+l"(d) : "l"(a))
__device__ __forceinline__ void unpack2(unsigned long long v, float& lo, float& hi) {
    asm("mov.b64 {%0, %1}, %2;" : "=f"(lo), "=f"(hi) : "l"(v));
}

// ============================================================================
// bf16 2-split conversion
// ============================================================================
__device__ __forceinline__ void split8(const float* f, uint4& hi, uint4& lo) {
    unsigned short hs[8], ls[8];
#pragma unroll
    for (int i = 0; i < 8; ++i) {
        __nv_bfloat16 h = __float2bfloat16_rn(f[i]);
        float rem = f[i] - __bfloat162float(h);
        __nv_bfloat16 l = __float2bfloat16_rn(rem);
        hs[i] = __bfloat16_as_ushort(h);
        ls[i] = __bfloat16_as_ushort(l);
    }
    hi.x = hs[0] | ((unsigned)hs[1] << 16); hi.y = hs[2] | ((unsigned)hs[3] << 16);
    hi.z = hs[4] | ((unsigned)hs[5] << 16); hi.w = hs[6] | ((unsigned)hs[7] << 16);
    lo.x = ls[0] | ((unsigned)ls[1] << 16); lo.y = ls[2] | ((unsigned)ls[3] << 16);
    lo.z = ls[4] | ((unsigned)ls[5] << 16); lo.w = ls[6] | ((unsigned)ls[7] << 16);
}

// x[b][t][k] -> planes[m = t*256+b][k]
__global__ void conv_x2_kernel(const float* __restrict__ x,
                               uint4* __restrict__ p0, uint4* __restrict__ p1)
{
    const size_t total = (size_t)64000 * 256;
    for (size_t u = (size_t)blockIdx.x * blockDim.x + threadIdx.x; u < total;
         u += (size_t)gridDim.x * blockDim.x) {
        const int m = (int)(u >> 8);
        const int g = (int)(u & 255);
        const int b = m & 255, t = m >> 8;
        const float* src = x + ((size_t)b * T_ + t) * 2048 + (size_t)g * 8;
        float f[8];
        *(float4*)&f[0] = *(const float4*)src;
        *(float4*)&f[4] = *(const float4*)(src + 4);
        uint4 hi, lo; split8(f, hi, lo);
        p0[u] = hi; p1[u] = lo;
    }
}

__global__ void conv_p2_kernel(const float* __restrict__ src,
                               uint4* __restrict__ p0, uint4* __restrict__ p1,
                               size_t n8)
{
    for (size_t u = (size_t)blockIdx.x * blockDim.x + threadIdx.x; u < n8;
         u += (size_t)gridDim.x * blockDim.x) {
        float f[8];
        const float* s = src + u * 8;
        *(float4*)&f[0] = *(const float4*)s;
        *(float4*)&f[4] = *(const float4*)(s + 4);
        uint4 hi, lo; split8(f, hi, lo);
        p0[u] = hi; p1[u] = lo;
    }
}

// ============================================================================
// Tensor-core GEMM (mma.sync, PROVEN in R7): C = (A0+A1) @ (W0+W1)^T + bias
// 2-split: hi*hi + hi*lo + lo*hi (lo*lo dropped, ~2^-18 relative).
// Tile 128x128x64, 256 thr (8 warps = 4m x 2n), cp.async double buffer.
// smem per plane: [128 rows][8 uint4], phys col = c ^ (row&7).  Planes:
// A0,A1 at 0,16K; W0,W1 at 32K,48K.
// ============================================================================
#define TC_BUF   65536                    // 4 planes x 16384 B
#define TC_SMEM  (2 * TC_BUF)             // 131072

__device__ __forceinline__ void ldsm4(unsigned r[4], unsigned addr) {
    asm volatile("ldmatrix.sync.aligned.m8n8.x4.shared.b16 {%0,%1,%2,%3}, [%4];"
                 : "=r"(r[0]), "=r"(r[1]), "=r"(r[2]), "=r"(r[3]) : "r"(addr));
}
__device__ __forceinline__ void mma_bf16(float* c, const unsigned* a, const unsigned* b) {
    asm volatile("mma.sync.aligned.m16n8k16.row.col.f32.bf16.bf16.f32 "
                 "{%0,%1,%2,%3}, {%4,%5,%6,%7}, {%8,%9}, {%0,%1,%2,%3};"
                 : "+f"(c[0]), "+f"(c[1]), "+f"(c[2]), "+f"(c[3])
                 : "r"(a[0]), "r"(a[1]), "r"(a[2]), "r"(a[3]), "r"(b[0]), "r"(b[1]));
}

__device__ __forceinline__ void tc_stage(const uint4* const gsrc[4], int ku4, int tid,
                                         unsigned sbuf, int it)
{
    const int k0 = it * 8;
#pragma unroll
    for (int arr = 0; arr < 4; ++arr) {
#pragma unroll
        for (int q = 0; q < 4; ++q) {
            const int idx = tid + q * 256;
            const int row = idx >> 3, c = idx & 7;
            const uint4* g = gsrc[arr] + (size_t)row * ku4 + k0 + c;
            unsigned s = sbuf + arr * 16384 + row * 128 + ((c ^ (row & 7)) << 4);
            asm volatile("cp.async.cg.shared.global [%0], [%1], 16;" :: "r"(s), "l"(g));
        }
    }
    asm volatile("cp.async.commit_group;");
}

__device__ __forceinline__ void tc_compute(unsigned sbuf, int wm, int wn,
                                           int lrow, int tb0, int tb1,
                                           float acc[2][8][4])
{
#pragma unroll
    for (int ks = 0; ks < 4; ++ks) {
        unsigned af[2][2][4];
        const unsigned pcA = (unsigned)(((ks * 2 + tb1) ^ lrow) << 4);
#pragma unroll
        for (int s = 0; s < 2; ++s)
#pragma unroll
            for (int i = 0; i < 2; ++i) {
                const int row = wm * 32 + i * 16 + lrow + tb0 * 8;
                ldsm4(af[s][i], sbuf + s * 16384 + row * 128 + pcA);
            }
        const unsigned pcB = (unsigned)(((ks * 2 + tb0) ^ lrow) << 4);
#pragma unroll
        for (int hh = 0; hh < 2; ++hh) {
            unsigned bfr[2][4][2];
#pragma unroll
            for (int s = 0; s < 2; ++s)
#pragma unroll
                for (int p = 0; p < 2; ++p) {
                    const int row = wn * 64 + (hh * 2 + p) * 16 + lrow + tb1 * 8;
                    unsigned r[4];
                    ldsm4(r, sbuf + 32768 + s * 16384 + row * 128 + pcB);
                    bfr[s][2 * p][0] = r[0];     bfr[s][2 * p][1] = r[1];
                    bfr[s][2 * p + 1][0] = r[2]; bfr[s][2 * p + 1][1] = r[3];
                }
#pragma unroll
            for (int i = 0; i < 2; ++i)
#pragma unroll
                for (int n = 0; n < 4; ++n) {
                    float* c = acc[i][hh * 4 + n];
                    mma_bf16(c, af[0][i], bfr[0][n]);   // hi*hi
                    mma_bf16(c, af[0][i], bfr[1][n]);   // hi*lo
                    mma_bf16(c, af[1][i], bfr[0][n]);   // lo*hi
                }
        }
    }
}

__global__ void __launch_bounds__(256) tc_gemm_kernel(
    const uint4* __restrict__ a0, const uint4* __restrict__ a1,
    const uint4* __restrict__ w0, const uint4* __restrict__ w1,
    const float* __restrict__ bias, float* __restrict__ C, int N, int K)
{
    extern __shared__ uint4 tcsm[];
    const unsigned sb = (unsigned)__cvta_generic_to_shared(tcsm);
    const int tid = threadIdx.x;
    const int m0 = blockIdx.y * 128, n0 = blockIdx.x * 128;
    const int ku4 = K >> 3;
    const int nIter = K >> 6;

    const uint4* gsrc[4] = {
        a0 + (size_t)m0 * ku4, a1 + (size_t)m0 * ku4,
        w0 + (size_t)n0 * ku4, w1 + (size_t)n0 * ku4 };

    const int warp = tid >> 5, l = tid & 31;
    const int wm = warp & 3, wn = warp >> 2;
    const int lrow = l & 7, tb0 = (l >> 3) & 1, tb1 = (l >> 4) & 1;

    float acc[2][8][4] = {};

    tc_stage(gsrc, ku4, tid, sb, 0);
    for (int it = 0; it < nIter; ++it) {
        asm volatile("cp.async.wait_group 0;");
        __syncthreads();
        if (it + 1 < nIter)
            tc_stage(gsrc, ku4, tid, sb + (unsigned)(((it + 1) & 1) * TC_BUF), it + 1);
        tc_compute(sb + (unsigned)((it & 1) * TC_BUF), wm, wn, lrow, tb0, tb1, acc);
        __syncthreads();
    }

    const int g = l >> 2, tq = (l & 3) * 2;
#pragma unroll
    for (int i = 0; i < 2; ++i)
#pragma unroll
        for (int n = 0; n < 8; ++n) {
            const int row = m0 + wm * 32 + i * 16 + g;
            const int col = n0 + wn * 64 + n * 8 + tq;
            const float b0 = bias[col], b1 = bias[col + 1];
            C[(size_t)row * N + col]           = acc[i][n][0] + b0;
            C[(size_t)row * N + col + 1]       = acc[i][n][1] + b1;
            C[(size_t)(row + 8) * N + col]     = acc[i][n][2] + b0;
            C[(size_t)(row + 8) * N + col + 1] = acc[i][n][3] + b1;
        }
}

// ============================================================================
// fp32 GEMM (FFMA2) — heads only (act 1/2), unchanged from R12
// ============================================================================
#define BM 128
#define BN 128
#define BK 16
#define ASTR 132
#define WSTR 140
__device__ __forceinline__ int wphys(int c) { return c + ((c >> 5) << 2); }

__device__ __forceinline__ void gemm_tile_compute(
    const float* __restrict__ As, const float* __restrict__ Ws,
    unsigned long long acc2[4][8], int tm, int wcol)
{
#pragma unroll
    for (int k = 0; k < BK; ++k) {
        ulonglong2 a01 = *(const ulonglong2*)&As[k * ASTR + tm * 8];
        ulonglong2 a23 = *(const ulonglong2*)&As[k * ASTR + tm * 8 + 4];
        float4 w0 = *(const float4*)&Ws[k * WSTR + wcol];
        float4 w1 = *(const float4*)&Ws[k * WSTR + wcol + 4];
        unsigned long long wd[8];
        wd[0] = dupf(w0.x); wd[1] = dupf(w0.y); wd[2] = dupf(w0.z); wd[3] = dupf(w0.w);
        wd[4] = dupf(w1.x); wd[5] = dupf(w1.y); wd[6] = dupf(w1.z); wd[7] = dupf(w1.w);
#pragma unroll
        for (int j = 0; j < 8; ++j) {
            FFMA2(acc2[0][j], a01.x, wd[j]);
            FFMA2(acc2[1][j], a01.y, wd[j]);
            FFMA2(acc2[2][j], a23.x, wd[j]);
            FFMA2(acc2[3][j], a23.y, wd[j]);
        }
    }
}

__global__ void __launch_bounds__(256, 2) gemm_kernel(
    const float* __restrict__ A, const float* __restrict__ W,
    const float* __restrict__ bias, float* __restrict__ C,
    int M, int N, int K, int act)
{
    __shared__ float As[2][BK * ASTR];
    __shared__ float Ws[2][BK * WSTR];
    const int tid = threadIdx.x;
    const int m0 = blockIdx.y * BM;
    const int n0 = blockIdx.x * BN;

    const int lr = tid >> 2;
    const int lk = (tid & 3) << 2;

    const float* pa0 = A + (long long)(m0 + lr) * K + lk;
    const float* pa1 = A + (long long)(m0 + lr + 64) * K + lk;
    const float* pw0 = W + (long long)(n0 + lr) * K + lk;
    const float* pw1 = W + (long long)(n0 + lr + 64) * K + lk;

    const int tm = tid >> 4;
    const int tn = tid & 15;
    const int wcol = tn * 8 + ((tn >> 2) << 2);
    const int wc0 = wphys(lr);
    const int wc1 = wphys(lr + 64);

    unsigned long long acc2[4][8];
#pragma unroll
    for (int i = 0; i < 4; ++i)
#pragma unroll
        for (int j = 0; j < 8; ++j) acc2[i][j] = 0ULL;

    {
        float4 a0 = *(const float4*)pa0;
        float4 a1 = *(const float4*)pa1;
        float4 w0 = *(const float4*)pw0;
        float4 w1 = *(const float4*)pw1;
        float av0[4] = {a0.x, a0.y, a0.z, a0.w};
        float av1[4] = {a1.x, a1.y, a1.z, a1.w};
        float wv0[4] = {w0.x, w0.y, w0.z, w0.w};
        float wv1[4] = {w1.x, w1.y, w1.z, w1.w};
#pragma unroll
        for (int j = 0; j < 4; ++j) {
            As[0][(lk + j) * ASTR + lr]      = av0[j];
            As[0][(lk + j) * ASTR + lr + 64] = av1[j];
            Ws[0][(lk + j) * WSTR + wc0]     = wv0[j];
            Ws[0][(lk + j) * WSTR + wc1]     = wv1[j];
        }
    }
    __syncthreads();

    const int nCh = K / BK;
    for (int c = 1; c < nCh; ++c) {
        const int off = c * BK;
        float4 na0 = *(const float4*)(pa0 + off);
        float4 na1 = *(const float4*)(pa1 + off);
        float4 nw0 = *(const float4*)(pw0 + off);
        float4 nw1 = *(const float4*)(pw1 + off);

        gemm_tile_compute(As[(c - 1) & 1], Ws[(c - 1) & 1], acc2, tm, wcol);

        const int wb = c & 1;
        float av0[4] = {na0.x, na0.y, na0.z, na0.w};
        float av1[4] = {na1.x, na1.y, na1.z, na1.w};
        float wv0[4] = {nw0.x, nw0.y, nw0.z, nw0.w};
        float wv1[4] = {nw1.x, nw1.y, nw1.z, nw1.w};
#pragma unroll
        for (int j = 0; j < 4; ++j) {
            As[wb][(lk + j) * ASTR + lr]      = av0[j];
            As[wb][(lk + j) * ASTR + lr + 64] = av1[j];
            Ws[wb][(lk + j) * WSTR + wc0]     = wv0[j];
            Ws[wb][(lk + j) * WSTR + wc1]     = wv1[j];
        }
        __syncthreads();
    }
    gemm_tile_compute(As[(nCh - 1) & 1], Ws[(nCh - 1) & 1], acc2, tm, wcol);

#pragma unroll
    for (int p = 0; p < 4; ++p) {
        float rowlo[8], rowhi[8];
#pragma unroll
        for (int j = 0; j < 8; ++j) {
            float lo, hi; unpack2(acc2[p][j], lo, hi);
            float bj = bias[n0 + tn * 8 + j];
            lo += bj; hi += bj;
            if (act == 1)      { lo = sigmf(lo); hi = sigmf(hi); }
            else if (act == 2) { lo = lo * sigmf(lo); hi = hi * sigmf(hi); }
            rowlo[j] = lo; rowhi[j] = hi;
        }
        const long long mA = m0 + tm * 8 + 2 * p;
        float* c0 = &C[mA * N + n0 + tn * 8];
        float* c1 = &C[(mA + 1) * N + n0 + tn * 8];
        *(float4*)c0       = make_float4(rowlo[0], rowlo[1], rowlo[2], rowlo[3]);
        *(float4*)(c0 + 4) = make_float4(rowlo[4], rowlo[5], rowlo[6], rowlo[7]);
        *(float4*)c1       = make_float4(rowhi[0], rowhi[1], rowhi[2], rowhi[3]);
        *(float4*)(c1 + 4) = make_float4(rowhi[4], rowhi[5], rowhi[6], rowhi[7]);
    }
}

// ============================================================================
// Persistent GRU scan — R12 version (best so far), unchanged.
// ============================================================================
#define GRU_W2_ULL   (3 * 256 * 16)
#define GRU_HT_F     (256 * 36)
#define GRU_PART_ULL (3 * 64 * 12)
#define GRU_SMEM     (GRU_W2_ULL * 8 + GRU_HT_F * 4 + GRU_PART_ULL * 8)

__global__ void __launch_bounds__(256, 1) gru_scan_kernel(
    const float* __restrict__ Whh, const float* __restrict__ bhh,
    const float* __restrict__ xg, float* __restrict__ hseq)
{
    extern __shared__ char smraw[];
    unsigned long long* w2  = (unsigned long long*)smraw;
    float*              hT  = (float*)(smraw + GRU_W2_ULL * 8);
    unsigned long long* prt = (unsigned long long*)(smraw + GRU_W2_ULL * 8 + GRU_HT_F * 4);

    const int tid = threadIdx.x;
    const int bg = blockIdx.x >> 4;
    const int b0 = bg * 32;
    const int h0 = (blockIdx.x & 15) * 16;
    const int c  = tid & 15;
    const int g  = (tid >> 4) & 3;
    const int ks = tid >> 6;
    const int r0 = g * 8;
    const int slot = (g << 4) | c;

    for (int idx = tid; idx < 48 * 64; idx += 256) {
        const int row = idx >> 6;
        const int k4  = (idx & 63) << 2;
        const int gate = row >> 4, cc = row & 15;
        float4 wv = *(const float4*)(Whh + (size_t)(gate * H_ + h0 + cc) * H_ + k4);
        w2[(gate * 256 + k4 + 0) * 16 + cc] = dupf(wv.x);
        w2[(gate * 256 + k4 + 1) * 16 + cc] = dupf(wv.y);
        w2[(gate * 256 + k4 + 2) * 16 + cc] = dupf(wv.z);
        w2[(gate * 256 + k4 + 3) * 16 + cc] = dupf(wv.w);
    }
    __syncthreads();

    const int hg = h0 + c;
    const float br = bhh[hg], bz = bhh[H_ + hg], bn = bhh[2 * H_ + hg];
    const int lr  = tid & 31;
    const int lk0 = (tid >> 5) * 32;

    unsigned long long* grp = &g_cntA[bg * 16];

    for (int t = 0; t < T_; ++t) {
        unsigned long long aR[4] = {0, 0, 0, 0}, aZ[4] = {0, 0, 0, 0}, aN[4] = {0, 0, 0, 0};
        float xv[3][8];

        if (ks == 0) {
            const float* xrow = xg + (size_t)t * (B_ * G3);
#pragma unroll
            for (int i = 0; i < 8; ++i) {
                const float* xr = xrow + (size_t)(b0 + r0 + i) * G3;
                xv[0][i] = xr[hg];
                xv[1][i] = xr[H_ + hg];
                xv[2][i] = xr[2 * H_ + hg];
            }
        }

        if (t > 0) {
            const float* src = hseq + (size_t)(t - 1) * (B_ * H_)
                                    + (size_t)(b0 + lr) * H_ + lk0;
#pragma unroll
            for (int q = 0; q < 8; ++q) {
                float4 v = __ldcg((const float4*)(src + q * 4));
                const int k = lk0 + q * 4;
                hT[(k + 0) * 36 + lr] = v.x;
                hT[(k + 1) * 36 + lr] = v.y;
                hT[(k + 2) * 36 + lr] = v.z;
                hT[(k + 3) * 36 + lr] = v.w;
            }
            __syncthreads();

            const int kb = ks * 64;
#pragma unroll 4
            for (int kk = 0; kk < 64; ++kk) {
                const int k = kb + kk;
                ulonglong2 a01 = *(const ulonglong2*)&hT[k * 36 + r0];
                ulonglong2 a23 = *(const ulonglong2*)&hT[k * 36 + r0 + 4];
                unsigned long long wr = w2[k * 16 + c];
                unsigned long long wz = w2[(256 + k) * 16 + c];
                unsigned long long wn = w2[(512 + k) * 16 + c];
                FFMA2(aR[0], a01.x, wr); FFMA2(aR[1], a01.y, wr);
                FFMA2(aR[2], a23.x, wr); FFMA2(aR[3], a23.y, wr);
                FFMA2(aZ[0], a01.x, wz); FFMA2(aZ[1], a01.y, wz);
                FFMA2(aZ[2], a23.x, wz); FFMA2(aZ[3], a23.y, wz);
                FFMA2(aN[0], a01.x, wn); FFMA2(aN[1], a01.y, wn);
                FFMA2(aN[2], a23.x, wn); FFMA2(aN[3], a23.y, wn);
            }

            if (ks != 0) {
                unsigned long long* p = prt + ((ks - 1) * 64 + slot) * 12;
#pragma unroll
                for (int i = 0; i < 4; ++i) { p[i] = aR[i]; p[4 + i] = aZ[i]; p[8 + i] = aN[i]; }
            }
            __syncthreads();
            if (ks == 0) {
#pragma unroll
                for (int q = 0; q < 3; ++q) {
                    const unsigned long long* p = prt + (q * 64 + slot) * 12;
#pragma unroll
                    for (int i = 0; i < 4; ++i) {
                        FADD2(aR[i], p[i]); FADD2(aZ[i], p[4 + i]); FADD2(aN[i], p[8 + i]);
                    }
                }
            }
        }

        if (ks == 0) {
            float rr[8], zz[8], nn[8], hold[8];
#pragma unroll
            for (int i = 0; i < 4; ++i) {
                unpack2(aR[i], rr[2 * i], rr[2 * i + 1]);
                unpack2(aZ[i], zz[2 * i], zz[2 * i + 1]);
                unpack2(aN[i], nn[2 * i], nn[2 * i + 1]);
            }
#pragma unroll
            for (int i = 0; i < 8; ++i)
                hold[i] = (t > 0) ? hT[hg * 36 + r0 + i] : 0.f;

            float* hout = hseq + (size_t)t * (B_ * H_);
#pragma unroll
            for (int i = 0; i < 8; ++i) {
                const float r = sigmf(xv[0][i] + rr[i] + br);
                const float z = sigmf(xv[1][i] + zz[i] + bz);
                const float n = tanhf(xv[2][i] + r * (nn[i] + bn));
                hout[(size_t)(b0 + r0 + i) * H_ + hg] = (1.f - z) * n + z * hold[i];
            }
        }

        if (t < T_ - 1) {
            __threadfence();
            __syncthreads();
            if (tid == 0) {
                atomicAdd(grp, 1ULL);
                const unsigned long long target =
                    (unsigned long long)(t + 1) * 16ULL;
                volatile unsigned long long* p = (volatile unsigned long long*)grp;
                while (*p < target) { }
                __threadfence();
            }
            __syncthreads();
        }
    }
}

__global__ void reset_sync_kernel() {
    if (threadIdx.x < 128) g_cntA[threadIdx.x] = 0ULL;
}

// ============================================================================
// Finalize per batch row: top-50 -> mask; softmax; mask+normalize; rebalance.
// ============================================================================
__global__ void __launch_bounds__(256) finalize_kernel(
    const float* __restrict__ att, const float* __restrict__ logits,
    float* __restrict__ out)
{
    __shared__ float a_s[NS];
    __shared__ float w_s[NS];
    __shared__ unsigned char m_s[NS];
    __shared__ float rf[256];
    __shared__ float rb[256];
    __shared__ int   ri[256];
    __shared__ float sc[8];

    const int b = blockIdx.x;
    const int tid = threadIdx.x;

    for (int n = tid; n < NS; n += 256) {
        a_s[n] = att[(long long)b * NS + n];
        w_s[n] = logits[(long long)b * NS + n];
        m_s[n] = 0;
    }
    if (tid == 0) sc[4] = 0.f;
    __syncthreads();

    for (int it = 0; it < NSEL; ++it) {
        float bv = -3.402823466e38f; int bi = 0x7fffffff;
        for (int n = tid; n < NS; n += 256) {
            float v = a_s[n];
            if (v > bv) { bv = v; bi = n; }
        }
        rf[tid] = bv; ri[tid] = bi;
        __syncthreads();
        for (int s = 128; s > 0; s >>= 1) {
            if (tid < s) {
                float v2 = rf[tid + s]; int i2 = ri[tid + s];
                if (v2 > rf[tid] || (v2 == rf[tid] && i2 < ri[tid])) { rf[tid] = v2; ri[tid] = i2; }
            }
            __syncthreads();
        }
        if (tid == 0) { m_s[ri[0]] = 1; a_s[ri[0]] = -3.402823466e38f; }
        __syncthreads();
    }

    float lm = -3.402823466e38f;
    for (int n = tid; n < NS; n += 256) lm = fmaxf(lm, w_s[n]);
    rf[tid] = lm; __syncthreads();
    for (int s = 128; s > 0; s >>= 1) { if (tid < s) rf[tid] = fmaxf(rf[tid], rf[tid + s]); __syncthreads(); }
    const float Mx = rf[0];
    __syncthreads();

    float ps = 0.f;
    for (int n = tid; n < NS; n += 256) { float e = expf(w_s[n] - Mx); w_s[n] = e; ps += e; }
    rf[tid] = ps; __syncthreads();
    for (int s = 128; s > 0; s >>= 1) { if (tid < s) rf[tid] += rf[tid + s]; __syncthreads(); }
    const float S = rf[0];
    __syncthreads();

    float pm = 0.f;
    for (int n = tid; n < NS; n += 256) {
        float mw = m_s[n] ? (w_s[n] / S) : 0.f;
        w_s[n] = mw; pm += mw;
    }
    rf[tid] = pm; __syncthreads();
    for (int s = 128; s > 0; s >>= 1) { if (tid < s) rf[tid] += rf[tid + s]; __syncthreads(); }
    const float SM = rf[0];
    __syncthreads();

    for (int n = tid; n < NS; n += 256) {
        float w0 = w_s[n] / (SM + 1e-8f);
        a_s[n] = w0;
        w_s[n] = fminf(fmaxf(w0, 0.f), UBv);
    }
    __syncthreads();

    for (int it = 0; it < RITER; ++it) {
        float pl = 0.f, pn = 0.f; int ph = 0;
        for (int n = tid; n < NS; n += 256) {
            float w = w_s[n];
            int nm = (w != UBv) && m_s[n];
            pl += a_s[n] - w;
            if (nm) { pn += w; ph = 1; }
        }
        rf[tid] = pl; rb[tid] = pn; ri[tid] = ph;
        __syncthreads();
        for (int s = 128; s > 0; s >>= 1) {
            if (tid < s) { rf[tid] += rf[tid + s]; rb[tid] += rb[tid + s]; ri[tid] |= ri[tid + s]; }
            __syncthreads();
        }
        if (tid == 0) { sc[0] = rf[0]; sc[1] = rb[0]; sc[2] = ri[0] ? 1.f : 0.f; }
        __syncthreads();

        const float leftover = sc[0];
        const float nsum = sc[1];
        const bool hasnom = (sc[2] != 0.f);
        const bool done = (sc[4] != 0.f);
        const bool upd = (!done) && hasnom;
        const float denom = (nsum == 0.f) ? 1.f : nsum;

        int po = 0;
        for (int n = tid; n < NS; n += 256) {
            float w = w_s[n];
            int nm = (w != UBv) && m_s[n];
            float gift = (leftover * (nm ? w : 0.f)) / denom;
            float w1 = upd ? (w + gift) : w;
            if (w1 > UBv) po = 1;
            w_s[n] = w1;
            if (upd) a_s[n] = w1;
        }
        ri[tid] = po;
        __syncthreads();
        for (int s = 128; s > 0; s >>= 1) { if (tid < s) ri[tid] |= ri[tid + s]; __syncthreads(); }
        const bool over = (ri[0] != 0);
        __syncthreads();

        if (upd && over)
            for (int n = tid; n < NS; n += 256)
                w_s[n] = fminf(fmaxf(w_s[n], 0.f), UBv);
        if (tid == 0) {
            bool d = done || ((!done) && (!hasnom)) || (upd && (!over));
            sc[4] = d ? 1.f : 0.f;
        }
        __syncthreads();
    }

    for (int n = tid; n < NS; n += 256)
        out[(long long)b * NS + n] = w_s[n];
}

// ============================================================================
extern "C" void kernel_launch(void* const* d_in, const int* in_sizes, int n_in,
                              void* d_out, int out_size)
{
    (void)in_sizes; (void)n_in; (void)out_size;
    const float* x    = (const float*)d_in[0];
    const float* Wih0 = (const float*)d_in[1];
    const float* Whh0 = (const float*)d_in[2];
    const float* bih0 = (const float*)d_in[3];
    const float* bhh0 = (const float*)d_in[4];
    const float* Wih1 = (const float*)d_in[5];
    const float* Whh1 = (const float*)d_in[6];
    const float* bih1 = (const float*)d_in[7];
    const float* bhh1 = (const float*)d_in[8];
    const float* Wa   = (const float*)d_in[9];
    const float* ba   = (const float*)d_in[10];
    const float* Wf   = (const float*)d_in[11];
    const float* bf   = (const float*)d_in[12];
    float* out = (float*)d_out;

    float *xg, *hseq, *attb, *logb;
    uint4 *a0, *a1, *w0, *w1;
    cudaGetSymbolAddress((void**)&xg,   g_xg);
    cudaGetSymbolAddress((void**)&hseq, g_hseq);
    cudaGetSymbolAddress((void**)&attb, g_att);
    cudaGetSymbolAddress((void**)&logb, g_log);
    cudaGetSymbolAddress((void**)&a0, g_a0);
    cudaGetSymbolAddress((void**)&a1, g_a1);
    cudaGetSymbolAddress((void**)&w0, g_w0);
    cudaGetSymbolAddress((void**)&w1, g_w1);

    cudaFuncSetAttribute(gru_scan_kernel,
                         cudaFuncAttributeMaxDynamicSharedMemorySize, GRU_SMEM);
    cudaFuncSetAttribute(tc_gemm_kernel,
                         cudaFuncAttributeMaxDynamicSharedMemorySize, TC_SMEM);

    const int M = T_ * B_;   // 64000

    // ---- xg0 = permute(x) @ Wih0^T + bih0  (mma.sync bf16 2-split) ----
    conv_x2_kernel<<<2048, 256>>>(x, a0, a1);
    conv_p2_kernel<<<768, 256>>>(Wih0, w0, w1, (size_t)G3 * 2048 / 8);
    tc_gemm_kernel<<<dim3(G3 / 128, M / 128), 256, TC_SMEM>>>(
        a0, a1, w0, w1, bih0, xg, G3, 2048);

    // GRU layer 0 (persistent, per-group atomic barrier)
    reset_sync_kernel<<<1, 128>>>();
    gru_scan_kernel<<<128, 256, GRU_SMEM>>>(Whh0, bhh0, xg, hseq);

    // ---- xg1 = hseq @ Wih1^T + bih1  (mma.sync bf16 2-split) ----
    conv_p2_kernel<<<2048, 256>>>(hseq, a0, a1, (size_t)M * H_ / 8);
    conv_p2_kernel<<<96, 256>>>(Wih1, w0, w1, (size_t)G3 * H_ / 8);
    tc_gemm_kernel<<<dim3(G3 / 128, M / 128), 256, TC_SMEM>>>(
        a0, a1, w0, w1, bih1, xg, G3, H_);

    // GRU layer 1 (persistent)
    reset_sync_kernel<<<1, 128>>>();
    gru_scan_kernel<<<128, 256, GRU_SMEM>>>(Whh1, bhh1, xg, hseq);

    const float* hT = hseq + (size_t)(T_ - 1) * B_ * H_;

    // heads (fp32 — accuracy-critical, tiny)
    gemm_kernel<<<dim3(NS / BN, B_ / BM), 256>>>(hT, Wa, ba, attb, B_, NS, H_, 1);
    gemm_kernel<<<dim3(NS / BN, B_ / BM), 256>>>(hT, Wf, bf, logb, B_, NS, H_, 2);

    finalize_kernel<<<B_, 256>>>(attb, logb, out);
}

// round 15
// speedup vs baseline: 1.9107x; 1.0430x over previous
#include <cuda_runtime.h>
#include <cuda_bf16.h>

#define B_   256
#define T_   250
#define NS   2048
#define H_   256
#define G3   768
#define NSEL 50
#define UBv  0.1f
#define RITER 32

// ---------------- scratch (device globals; no runtime alloc) ----------------
__device__ float g_xg[(size_t)T_ * B_ * G3];     // xg0
__device__ float g_hbuf[5 * B_ * H_];            // h0 ping-pong, h1 ping-pong, hfin
__device__ float g_att[B_ * NS];
__device__ float g_log[B_ * NS];
__device__ unsigned long long g_cntA[128];       // 8 group counters, 128B apart

// bf16 2-split planes
__device__ uint4 g_a0[16384000];
__device__ uint4 g_a1[16384000];
__device__ uint4 g_w0[196608];
__device__ uint4 g_w1[196608];

__device__ __forceinline__ float sigmf(float x) { return 1.f / (1.f + expf(-x)); }

__device__ __forceinline__ unsigned long long dupf(float x) {
    unsigned long long r;
    asm("mov.b64 %0, {%1, %1};" : "=l"(r) : "f"(x));
    return r;
}
#define FFMA2(d, a, b) asm("fma.rn.f32x2 %0, %1, %2, %0;" : "+l"(d) : "l"(a), "l"(b))
#define FADD2(d, a)    asm("add.rn.f32x2 %0, %0, %1;"     : "+l"(d) : "l"(a))
__device__ __forceinline__ void unpack2(unsigned long long v, float& lo, float& hi) {
    asm("mov.b64 {%0, %1}, %2;" : "=f"(lo), "=f"(hi) : "l"(v));
}

// ============================================================================
// bf16 2-split conversion (xg0 path only)
// ============================================================================
__device__ __forceinline__ void split8(const float* f, uint4& hi, uint4& lo) {
    unsigned short hs[8], ls[8];
#pragma unroll
    for (int i = 0; i < 8; ++i) {
        __nv_bfloat16 h = __float2bfloat16_rn(f[i]);
        float rem = f[i] - __bfloat162float(h);
        __nv_bfloat16 l = __float2bfloat16_rn(rem);
        hs[i] = __bfloat16_as_ushort(h);
        ls[i] = __bfloat16_as_ushort(l);
    }
    hi.x = hs[0] | ((unsigned)hs[1] << 16); hi.y = hs[2] | ((unsigned)hs[3] << 16);
    hi.z = hs[4] | ((unsigned)hs[5] << 16); hi.w = hs[6] | ((unsigned)hs[7] << 16);
    lo.x = ls[0] | ((unsigned)ls[1] << 16); lo.y = ls[2] | ((unsigned)ls[3] << 16);
    lo.z = ls[4] | ((unsigned)ls[5] << 16); lo.w = ls[6] | ((unsigned)ls[7] << 16);
}

__global__ void conv_x2_kernel(const float* __restrict__ x,
                               uint4* __restrict__ p0, uint4* __restrict__ p1)
{
    const size_t total = (size_t)64000 * 256;
    for (size_t u = (size_t)blockIdx.x * blockDim.x + threadIdx.x; u < total;
         u += (size_t)gridDim.x * blockDim.x) {
        const int m = (int)(u >> 8);
        const int g = (int)(u & 255);
        const int b = m & 255, t = m >> 8;
        const float* src = x + ((size_t)b * T_ + t) * 2048 + (size_t)g * 8;
        float f[8];
        *(float4*)&f[0] = *(const float4*)src;
        *(float4*)&f[4] = *(const float4*)(src + 4);
        uint4 hi, lo; split8(f, hi, lo);
        p0[u] = hi; p1[u] = lo;
    }
}

__global__ void conv_p2_kernel(const float* __restrict__ src,
                               uint4* __restrict__ p0, uint4* __restrict__ p1,
                               size_t n8)
{
    for (size_t u = (size_t)blockIdx.x * blockDim.x + threadIdx.x; u < n8;
         u += (size_t)gridDim.x * blockDim.x) {
        float f[8];
        const float* s = src + u * 8;
        *(float4*)&f[0] = *(const float4*)s;
        *(float4*)&f[4] = *(const float4*)(s + 4);
        uint4 hi, lo; split8(f, hi, lo);
        p0[u] = hi; p1[u] = lo;
    }
}

// ============================================================================
// Tensor-core GEMM (mma.sync bf16 2-split) — xg0 only (proven R14)
// ============================================================================
#define TC_BUF   65536
#define TC_SMEM  (2 * TC_BUF)

__device__ __forceinline__ void ldsm4(unsigned r[4], unsigned addr) {
    asm volatile("ldmatrix.sync.aligned.m8n8.x4.shared.b16 {%0,%1,%2,%3}, [%4];"
                 : "=r"(r[0]), "=r"(r[1]), "=r"(r[2]), "=r"(r[3]) : "r"(addr));
}
__device__ __forceinline__ void mma_bf16(float* c, const unsigned* a, const unsigned* b) {
    asm volatile("mma.sync.aligned.m16n8k16.row.col.f32.bf16.bf16.f32 "
                 "{%0,%1,%2,%3}, {%4,%5,%6,%7}, {%8,%9}, {%0,%1,%2,%3};"
                 : "+f"(c[0]), "+f"(c[1]), "+f"(c[2]), "+f"(c[3])
                 : "r"(a[0]), "r"(a[1]), "r"(a[2]), "r"(a[3]), "r"(b[0]), "r"(b[1]));
}

__device__ __forceinline__ void tc_stage(const uint4* const gsrc[4], int ku4, int tid,
                                         unsigned sbuf, int it)
{
    const int k0 = it * 8;
#pragma unroll
    for (int arr = 0; arr < 4; ++arr) {
#pragma unroll
        for (int q = 0; q < 4; ++q) {
            const int idx = tid + q * 256;
            const int row = idx >> 3, c = idx & 7;
            const uint4* g = gsrc[arr] + (size_t)row * ku4 + k0 + c;
            unsigned s = sbuf + arr * 16384 + row * 128 + ((c ^ (row & 7)) << 4);
            asm volatile("cp.async.cg.shared.global [%0], [%1], 16;" :: "r"(s), "l"(g));
        }
    }
    asm volatile("cp.async.commit_group;");
}

__device__ __forceinline__ void tc_compute(unsigned sbuf, int wm, int wn,
                                           int lrow, int tb0, int tb1,
                                           float acc[2][8][4])
{
#pragma unroll
    for (int ks = 0; ks < 4; ++ks) {
        unsigned af[2][2][4];
        const unsigned pcA = (unsigned)(((ks * 2 + tb1) ^ lrow) << 4);
#pragma unroll
        for (int s = 0; s < 2; ++s)
#pragma unroll
            for (int i = 0; i < 2; ++i) {
                const int row = wm * 32 + i * 16 + lrow + tb0 * 8;
                ldsm4(af[s][i], sbuf + s * 16384 + row * 128 + pcA);
            }
        const unsigned pcB = (unsigned)(((ks * 2 + tb0) ^ lrow) << 4);
#pragma unroll
        for (int hh = 0; hh < 2; ++hh) {
            unsigned bfr[2][4][2];
#pragma unroll
            for (int s = 0; s < 2; ++s)
#pragma unroll
                for (int p = 0; p < 2; ++p) {
                    const int row = wn * 64 + (hh * 2 + p) * 16 + lrow + tb1 * 8;
                    unsigned r[4];
                    ldsm4(r, sbuf + 32768 + s * 16384 + row * 128 + pcB);
                    bfr[s][2 * p][0] = r[0];     bfr[s][2 * p][1] = r[1];
                    bfr[s][2 * p + 1][0] = r[2]; bfr[s][2 * p + 1][1] = r[3];
                }
#pragma unroll
            for (int i = 0; i < 2; ++i)
#pragma unroll
                for (int n = 0; n < 4; ++n) {
                    float* c = acc[i][hh * 4 + n];
                    mma_bf16(c, af[0][i], bfr[0][n]);
                    mma_bf16(c, af[0][i], bfr[1][n]);
                    mma_bf16(c, af[1][i], bfr[0][n]);
                }
        }
    }
}

__global__ void __launch_bounds__(256) tc_gemm_kernel(
    const uint4* __restrict__ a0, const uint4* __restrict__ a1,
    const uint4* __restrict__ w0, const uint4* __restrict__ w1,
    const float* __restrict__ bias, float* __restrict__ C, int N, int K)
{
    extern __shared__ uint4 tcsm[];
    const unsigned sb = (unsigned)__cvta_generic_to_shared(tcsm);
    const int tid = threadIdx.x;
    const int m0 = blockIdx.y * 128, n0 = blockIdx.x * 128;
    const int ku4 = K >> 3;
    const int nIter = K >> 6;

    const uint4* gsrc[4] = {
        a0 + (size_t)m0 * ku4, a1 + (size_t)m0 * ku4,
        w0 + (size_t)n0 * ku4, w1 + (size_t)n0 * ku4 };

    const int warp = tid >> 5, l = tid & 31;
    const int wm = warp & 3, wn = warp >> 2;
    const int lrow = l & 7, tb0 = (l >> 3) & 1, tb1 = (l >> 4) & 1;

    float acc[2][8][4] = {};

    tc_stage(gsrc, ku4, tid, sb, 0);
    for (int it = 0; it < nIter; ++it) {
        asm volatile("cp.async.wait_group 0;");
        __syncthreads();
        if (it + 1 < nIter)
            tc_stage(gsrc, ku4, tid, sb + (unsigned)(((it + 1) & 1) * TC_BUF), it + 1);
        tc_compute(sb + (unsigned)((it & 1) * TC_BUF), wm, wn, lrow, tb0, tb1, acc);
        __syncthreads();
    }

    const int g = l >> 2, tq = (l & 3) * 2;
#pragma unroll
    for (int i = 0; i < 2; ++i)
#pragma unroll
        for (int n = 0; n < 8; ++n) {
            const int row = m0 + wm * 32 + i * 16 + g;
            const int col = n0 + wn * 64 + n * 8 + tq;
            const float b0 = bias[col], b1 = bias[col + 1];
            C[(size_t)row * N + col]           = acc[i][n][0] + b0;
            C[(size_t)row * N + col + 1]       = acc[i][n][1] + b1;
            C[(size_t)(row + 8) * N + col]     = acc[i][n][2] + b0;
            C[(size_t)(row + 8) * N + col + 1] = acc[i][n][3] + b1;
        }
}

// ============================================================================
// FUSED persistent scan: both GRU layers + xg1 matvec, 1-step skew.
// 128 blocks = 8 batch-groups(32 rows) x 16 hcol-tiles(16 hcols), 384 thr.
// Warps: sel = warp%3 (0=L0 gates, 1=XG1, 2=L1 gates), g = warp/3 (8 rows).
// Lane: c = lane&15 (hcol), ks = lane>>4 (k half). Shuffle-reduce k halves.
// Weights (Whh0, Wih1, Whh1) f32 in smem [k 256][48]; h tiles [k 256][36].
// Step s: L0 -> h0(s) [s=0..249]; XG1 -> xg1(s-1) [s=1..250];
//         L1 -> h1(s-1) [s=1..250].  251 steps, 250 group barriers.
// ============================================================================
#define SCF_W_F   (3 * 256 * 48)
#define SCF_HT_F  (256 * 36)
#define SCF_XGB_F (32 * 48)
#define SCF_SMEM  ((SCF_W_F + 2 * SCF_HT_F + SCF_XGB_F) * 4)   // 227328

__global__ void __launch_bounds__(384, 1) gru_fused_kernel(
    const float* __restrict__ Whh0, const float* __restrict__ bhh0,
    const float* __restrict__ Wih1, const float* __restrict__ bih1,
    const float* __restrict__ Whh1, const float* __restrict__ bhh1,
    const float* __restrict__ xg0,
    float* __restrict__ h0p, float* __restrict__ h1p, float* __restrict__ hfin)
{
    extern __shared__ float sm[];
    float* Wsm = sm;                         // [sel][256][48]
    float* h0T = sm + SCF_W_F;               // [256][36]
    float* h1T = h0T + SCF_HT_F;
    float* xgb = h1T + SCF_HT_F;             // [32 rows][48]

    const int tid = threadIdx.x;
    const int bg = blockIdx.x >> 4;
    const int b0 = bg * 32;
    const int h0c = (blockIdx.x & 15) * 16;
    const int warp = tid >> 5, lane = tid & 31;
    const int sel = warp % 3;                // 0=L0, 1=XG1, 2=L1
    const int g  = warp / 3;                 // 0..3
    const int c  = lane & 15;
    const int ks = lane >> 4;
    const int r0 = g * 8;
    const int hg = h0c + c;

    // ---- one-time weight loads: [k][gate*16+cc] transposed slices ----
    const float* wsrc[3] = {Whh0, Wih1, Whh1};
    for (int idx = tid; idx < 3 * 48 * 64; idx += 384) {
        const int wi = idx / (48 * 64);
        const int rem = idx % (48 * 64);
        const int row = rem >> 6;            // 0..47
        const int k4  = (rem & 63) << 2;
        const int gate = row >> 4, cc = row & 15;
        float4 wv = *(const float4*)(wsrc[wi] + (size_t)(gate * H_ + h0c + cc) * H_ + k4);
        float w[4] = {wv.x, wv.y, wv.z, wv.w};
#pragma unroll
        for (int j = 0; j < 4; ++j)
            Wsm[wi * 12288 + (k4 + j) * 48 + gate * 16 + cc] = w[j];
    }

    // per-lane biases by role
    const float* bsrc = (sel == 0) ? bhh0 : (sel == 1) ? bih1 : bhh1;
    const float bR = bsrc[hg], bZ = bsrc[H_ + hg], bN = bsrc[2 * H_ + hg];

    __syncthreads();

    unsigned long long* grp = &g_cntA[bg * 16];
    const int sr = tid & 31;                 // staging row (first 256 thr)
    const int sk = (tid >> 5) * 32;          // staging k base

    for (int s = 0; s <= T_; ++s) {
        // xg0 inputs for L0 epilogue (overlaps staging/k-loop latency)
        float xv[3][8];
        if (sel == 0 && lane < 16 && s < T_) {
            const float* xrow = xg0 + (size_t)s * (B_ * G3);
#pragma unroll
            for (int i = 0; i < 8; ++i) {
                const float* xr = xrow + (size_t)(b0 + r0 + i) * G3;
                xv[0][i] = xr[hg]; xv[1][i] = xr[H_ + hg]; xv[2][i] = xr[2 * H_ + hg];
            }
        }

        // ---- stage h0(s-1) (thr 0..255) and h1(s-2) (thr 128..383) ----
        if (s >= 1) {
            if (tid < 256) {
                const float* src = h0p + (size_t)((s - 1) & 1) * (B_ * H_)
                                       + (size_t)(b0 + sr) * H_ + sk;
#pragma unroll
                for (int q = 0; q < 8; ++q) {
                    float4 v = __ldcg((const float4*)(src + q * 4));
                    const int k = sk + q * 4;
                    h0T[(k + 0) * 36 + sr] = v.x;
                    h0T[(k + 1) * 36 + sr] = v.y;
                    h0T[(k + 2) * 36 + sr] = v.z;
                    h0T[(k + 3) * 36 + sr] = v.w;
                }
            }
            if (s >= 2 && tid >= 128) {
                const int t2 = tid - 128;
                const int lr2 = t2 & 31, lk2 = (t2 >> 5) * 32;
                const float* src = h1p + (size_t)((s - 2) & 1) * (B_ * H_)
                                       + (size_t)(b0 + lr2) * H_ + lk2;
#pragma unroll
                for (int q = 0; q < 8; ++q) {
                    float4 v = __ldcg((const float4*)(src + q * 4));
                    const int k = lk2 + q * 4;
                    h1T[(k + 0) * 36 + lr2] = v.x;
                    h1T[(k + 1) * 36 + lr2] = v.y;
                    h1T[(k + 2) * 36 + lr2] = v.z;
                    h1T[(k + 3) * 36 + lr2] = v.w;
                }
            }
            __syncthreads();
        }

        // ---- k-loop: three same-shape matvecs ----
        unsigned long long aR[4] = {0, 0, 0, 0}, aZ[4] = {0, 0, 0, 0}, aN[4] = {0, 0, 0, 0};
        const bool act = (sel == 0) ? (s >= 1 && s < T_)
                       : (sel == 1) ? (s >= 1)
                                    : (s >= 2);
        if (act) {
            const float* A = (sel == 2) ? h1T : h0T;
            const float* W = Wsm + sel * 12288;
            const int kb = ks * 128;
#pragma unroll 8
            for (int kk = 0; kk < 128; ++kk) {
                const int k = kb + kk;
                ulonglong2 a01 = *(const ulonglong2*)&A[k * 36 + r0];
                ulonglong2 a23 = *(const ulonglong2*)&A[k * 36 + r0 + 4];
                unsigned long long wr = dupf(W[k * 48 + c]);
                unsigned long long wz = dupf(W[k * 48 + 16 + c]);
                unsigned long long wn = dupf(W[k * 48 + 32 + c]);
                FFMA2(aR[0], a01.x, wr); FFMA2(aR[1], a01.y, wr);
                FFMA2(aR[2], a23.x, wr); FFMA2(aR[3], a23.y, wr);
                FFMA2(aZ[0], a01.x, wz); FFMA2(aZ[1], a01.y, wz);
                FFMA2(aZ[2], a23.x, wz); FFMA2(aZ[3], a23.y, wz);
                FFMA2(aN[0], a01.x, wn); FFMA2(aN[1], a01.y, wn);
                FFMA2(aN[2], a23.x, wn); FFMA2(aN[3], a23.y, wn);
            }
        }
        // shuffle-reduce ks=1 -> ks=0
#pragma unroll
        for (int i = 0; i < 4; ++i) {
            unsigned long long o;
            o = __shfl_down_sync(0xffffffffu, aR[i], 16); FADD2(aR[i], o);
            o = __shfl_down_sync(0xffffffffu, aZ[i], 16); FADD2(aZ[i], o);
            o = __shfl_down_sync(0xffffffffu, aN[i], 16); FADD2(aN[i], o);
        }

        // XG1 publishes xg1(s-1) to smem
        if (sel == 1 && lane < 16 && s >= 1) {
            float rr[8], zz[8], nn[8];
#pragma unroll
            for (int i = 0; i < 4; ++i) {
                unpack2(aR[i], rr[2 * i], rr[2 * i + 1]);
                unpack2(aZ[i], zz[2 * i], zz[2 * i + 1]);
                unpack2(aN[i], nn[2 * i], nn[2 * i + 1]);
            }
#pragma unroll
            for (int i = 0; i < 8; ++i) {
                xgb[(r0 + i) * 48 + c]      = rr[i] + bR;
                xgb[(r0 + i) * 48 + 16 + c] = zz[i] + bZ;
                xgb[(r0 + i) * 48 + 32 + c] = nn[i] + bN;
            }
        }
        __syncthreads();

        // L0 epilogue: h0(s)
        if (sel == 0 && lane < 16 && s < T_) {
            float rr[8], zz[8], nn[8];
#pragma unroll
            for (int i = 0; i < 4; ++i) {
                unpack2(aR[i], rr[2 * i], rr[2 * i + 1]);
                unpack2(aZ[i], zz[2 * i], zz[2 * i + 1]);
                unpack2(aN[i], nn[2 * i], nn[2 * i + 1]);
            }
            float* dst = h0p + (size_t)(s & 1) * (B_ * H_);
#pragma unroll
            for (int i = 0; i < 8; ++i) {
                const float hold = (s >= 1) ? h0T[hg * 36 + r0 + i] : 0.f;
                const float r = sigmf(xv[0][i] + rr[i] + bR);
                const float z = sigmf(xv[1][i] + zz[i] + bZ);
                const float n = tanhf(xv[2][i] + r * (nn[i] + bN));
                dst[(size_t)(b0 + r0 + i) * H_ + hg] = (1.f - z) * n + z * hold;
            }
        }
        // L1 epilogue: h1(s-1)
        if (sel == 2 && lane < 16 && s >= 1) {
            float rr[8], zz[8], nn[8];
#pragma unroll
            for (int i = 0; i < 4; ++i) {
                unpack2(aR[i], rr[2 * i], rr[2 * i + 1]);
                unpack2(aZ[i], zz[2 * i], zz[2 * i + 1]);
                unpack2(aN[i], nn[2 * i], nn[2 * i + 1]);
            }
            float* dst = h1p + (size_t)((s - 1) & 1) * (B_ * H_);
#pragma unroll
            for (int i = 0; i < 8; ++i) {
                const float hold = (s >= 2) ? h1T[hg * 36 + r0 + i] : 0.f;
                const float xr = xgb[(r0 + i) * 48 + c];
                const float xz = xgb[(r0 + i) * 48 + 16 + c];
                const float xn = xgb[(r0 + i) * 48 + 32 + c];
                const float r = sigmf(xr + rr[i] + bR);
                const float z = sigmf(xz + zz[i] + bZ);
                const float n = tanhf(xn + r * (nn[i] + bN));
                const float h = (1.f - z) * n + z * hold;
                dst[(size_t)(b0 + r0 + i) * H_ + hg] = h;
                if (s == T_)
                    hfin[(size_t)(b0 + r0 + i) * H_ + hg] = h;
            }
        }

        if (s < T_) {
            __threadfence();
            __syncthreads();
            if (tid == 0) {
                atomicAdd(grp, 1ULL);
                const unsigned long long target = (unsigned long long)(s + 1) * 16ULL;
                volatile unsigned long long* p = (volatile unsigned long long*)grp;
                while (*p < target) { }
                __threadfence();
            }
            __syncthreads();
        }
    }
}

__global__ void reset_sync_kernel() {
    if (threadIdx.x < 128) g_cntA[threadIdx.x] = 0ULL;
}

// ============================================================================
// fp32 GEMM (FFMA2) — heads only
// ============================================================================
#define BM 128
#define BN 128
#define BK 16
#define ASTR 132
#define WSTR 140
__device__ __forceinline__ int wphys(int c) { return c + ((c >> 5) << 2); }

__device__ __forceinline__ void gemm_tile_compute(
    const float* __restrict__ As, const float* __restrict__ Ws,
    unsigned long long acc2[4][8], int tm, int wcol)
{
#pragma unroll
    for (int k = 0; k < BK; ++k) {
        ulonglong2 a01 = *(const ulonglong2*)&As[k * ASTR + tm * 8];
        ulonglong2 a23 = *(const ulonglong2*)&As[k * ASTR + tm * 8 + 4];
        float4 w0 = *(const float4*)&Ws[k * WSTR + wcol];
        float4 w1 = *(const float4*)&Ws[k * WSTR + wcol + 4];
        unsigned long long wd[8];
        wd[0] = dupf(w0.x); wd[1] = dupf(w0.y); wd[2] = dupf(w0.z); wd[3] = dupf(w0.w);
        wd[4] = dupf(w1.x); wd[5] = dupf(w1.y); wd[6] = dupf(w1.z); wd[7] = dupf(w1.w);
#pragma unroll
        for (int j = 0; j < 8; ++j) {
            FFMA2(acc2[0][j], a01.x, wd[j]);
            FFMA2(acc2[1][j], a01.y, wd[j]);
            FFMA2(acc2[2][j], a23.x, wd[j]);
            FFMA2(acc2[3][j], a23.y, wd[j]);
        }
    }
}

__global__ void __launch_bounds__(256, 2) gemm_kernel(
    const float* __restrict__ A, const float* __restrict__ W,
    const float* __restrict__ bias, float* __restrict__ C,
    int M, int N, int K, int act)
{
    __shared__ float As[2][BK * ASTR];
    __shared__ float Ws[2][BK * WSTR];
    const int tid = threadIdx.x;
    const int m0 = blockIdx.y * BM;
    const int n0 = blockIdx.x * BN;

    const int lr = tid >> 2;
    const int lk = (tid & 3) << 2;

    const float* pa0 = A + (long long)(m0 + lr) * K + lk;
    const float* pa1 = A + (long long)(m0 + lr + 64) * K + lk;
    const float* pw0 = W + (long long)(n0 + lr) * K + lk;
    const float* pw1 = W + (long long)(n0 + lr + 64) * K + lk;

    const int tm = tid >> 4;
    const int tn = tid & 15;
    const int wcol = tn * 8 + ((tn >> 2) << 2);
    const int wc0 = wphys(lr);
    const int wc1 = wphys(lr + 64);

    unsigned long long acc2[4][8];
#pragma unroll
    for (int i = 0; i < 4; ++i)
#pragma unroll
        for (int j = 0; j < 8; ++j) acc2[i][j] = 0ULL;

    {
        float4 a0 = *(const float4*)pa0;
        float4 a1 = *(const float4*)pa1;
        float4 w0 = *(const float4*)pw0;
        float4 w1 = *(const float4*)pw1;
        float av0[4] = {a0.x, a0.y, a0.z, a0.w};
        float av1[4] = {a1.x, a1.y, a1.z, a1.w};
        float wv0[4] = {w0.x, w0.y, w0.z, w0.w};
        float wv1[4] = {w1.x, w1.y, w1.z, w1.w};
#pragma unroll
        for (int j = 0; j < 4; ++j) {
            As[0][(lk + j) * ASTR + lr]      = av0[j];
            As[0][(lk + j) * ASTR + lr + 64] = av1[j];
            Ws[0][(lk + j) * WSTR + wc0]     = wv0[j];
            Ws[0][(lk + j) * WSTR + wc1]     = wv1[j];
        }
    }
    __syncthreads();

    const int nCh = K / BK;
    for (int c = 1; c < nCh; ++c) {
        const int off = c * BK;
        float4 na0 = *(const float4*)(pa0 + off);
        float4 na1 = *(const float4*)(pa1 + off);
        float4 nw0 = *(const float4*)(pw0 + off);
        float4 nw1 = *(const float4*)(pw1 + off);

        gemm_tile_compute(As[(c - 1) & 1], Ws[(c - 1) & 1], acc2, tm, wcol);

        const int wb = c & 1;
        float av0[4] = {na0.x, na0.y, na0.z, na0.w};
        float av1[4] = {na1.x, na1.y, na1.z, na1.w};
        float wv0[4] = {nw0.x, nw0.y, nw0.z, nw0.w};
        float wv1[4] = {nw1.x, nw1.y, nw1.z, nw1.w};
#pragma unroll
        for (int j = 0; j < 4; ++j) {
            As[wb][(lk + j) * ASTR + lr]      = av0[j];
            As[wb][(lk + j) * ASTR + lr + 64] = av1[j];
            Ws[wb][(lk + j) * WSTR + wc0]     = wv0[j];
            Ws[wb][(lk + j) * WSTR + wc1]     = wv1[j];
        }
        __syncthreads();
    }
    gemm_tile_compute(As[(nCh - 1) & 1], Ws[(nCh - 1) & 1], acc2, tm, wcol);

#pragma unroll
    for (int p = 0; p < 4; ++p) {
        float rowlo[8], rowhi[8];
#pragma unroll
        for (int j = 0; j < 8; ++j) {
            float lo, hi; unpack2(acc2[p][j], lo, hi);
            float bj = bias[n0 + tn * 8 + j];
            lo += bj; hi += bj;
            if (act == 1)      { lo = sigmf(lo); hi = sigmf(hi); }
            else if (act == 2) { lo = lo * sigmf(lo); hi = hi * sigmf(hi); }
            rowlo[j] = lo; rowhi[j] = hi;
        }
        const long long mA = m0 + tm * 8 + 2 * p;
        float* c0 = &C[mA * N + n0 + tn * 8];
        float* c1 = &C[(mA + 1) * N + n0 + tn * 8];
        *(float4*)c0       = make_float4(rowlo[0], rowlo[1], rowlo[2], rowlo[3]);
        *(float4*)(c0 + 4) = make_float4(rowlo[4], rowlo[5], rowlo[6], rowlo[7]);
        *(float4*)c1       = make_float4(rowhi[0], rowhi[1], rowhi[2], rowhi[3]);
        *(float4*)(c1 + 4) = make_float4(rowhi[4], rowhi[5], rowhi[6], rowhi[7]);
    }
}

// ============================================================================
// Finalize per batch row: top-50 -> mask; softmax; mask+normalize; rebalance.
// ============================================================================
__global__ void __launch_bounds__(256) finalize_kernel(
    const float* __restrict__ att, const float* __restrict__ logits,
    float* __restrict__ out)
{
    __shared__ float a_s[NS];
    __shared__ float w_s[NS];
    __shared__ unsigned char m_s[NS];
    __shared__ float rf[256];
    __shared__ float rb[256];
    __shared__ int   ri[256];
    __shared__ float sc[8];

    const int b = blockIdx.x;
    const int tid = threadIdx.x;

    for (int n = tid; n < NS; n += 256) {
        a_s[n] = att[(long long)b * NS + n];
        w_s[n] = logits[(long long)b * NS + n];
        m_s[n] = 0;
    }
    if (tid == 0) sc[4] = 0.f;
    __syncthreads();

    for (int it = 0; it < NSEL; ++it) {
        float bv = -3.402823466e38f; int bi = 0x7fffffff;
        for (int n = tid; n < NS; n += 256) {
            float v = a_s[n];
            if (v > bv) { bv = v; bi = n; }
        }
        rf[tid] = bv; ri[tid] = bi;
        __syncthreads();
        for (int s = 128; s > 0; s >>= 1) {
            if (tid < s) {
                float v2 = rf[tid + s]; int i2 = ri[tid + s];
                if (v2 > rf[tid] || (v2 == rf[tid] && i2 < ri[tid])) { rf[tid] = v2; ri[tid] = i2; }
            }
            __syncthreads();
        }
        if (tid == 0) { m_s[ri[0]] = 1; a_s[ri[0]] = -3.402823466e38f; }
        __syncthreads();
    }

    float lm = -3.402823466e38f;
    for (int n = tid; n < NS; n += 256) lm = fmaxf(lm, w_s[n]);
    rf[tid] = lm; __syncthreads();
    for (int s = 128; s > 0; s >>= 1) { if (tid < s) rf[tid] = fmaxf(rf[tid], rf[tid + s]); __syncthreads(); }
    const float Mx = rf[0];
    __syncthreads();

    float ps = 0.f;
    for (int n = tid; n < NS; n += 256) { float e = expf(w_s[n] - Mx); w_s[n] = e; ps += e; }
    rf[tid] = ps; __syncthreads();
    for (int s = 128; s > 0; s >>= 1) { if (tid < s) rf[tid] += rf[tid + s]; __syncthreads(); }
    const float S = rf[0];
    __syncthreads();

    float pm = 0.f;
    for (int n = tid; n < NS; n += 256) {
        float mw = m_s[n] ? (w_s[n] / S) : 0.f;
        w_s[n] = mw; pm += mw;
    }
    rf[tid] = pm; __syncthreads();
    for (int s = 128; s > 0; s >>= 1) { if (tid < s) rf[tid] += rf[tid + s]; __syncthreads(); }
    const float SM = rf[0];
    __syncthreads();

    for (int n = tid; n < NS; n += 256) {
        float w0 = w_s[n] / (SM + 1e-8f);
        a_s[n] = w0;
        w_s[n] = fminf(fmaxf(w0, 0.f), UBv);
    }
    __syncthreads();

    for (int it = 0; it < RITER; ++it) {
        float pl = 0.f, pn = 0.f; int ph = 0;
        for (int n = tid; n < NS; n += 256) {
            float w = w_s[n];
            int nm = (w != UBv) && m_s[n];
            pl += a_s[n] - w;
            if (nm) { pn += w; ph = 1; }
        }
        rf[tid] = pl; rb[tid] = pn; ri[tid] = ph;
        __syncthreads();
        for (int s = 128; s > 0; s >>= 1) {
            if (tid < s) { rf[tid] += rf[tid + s]; rb[tid] += rb[tid + s]; ri[tid] |= ri[tid + s]; }
            __syncthreads();
        }
        if (tid == 0) { sc[0] = rf[0]; sc[1] = rb[0]; sc[2] = ri[0] ? 1.f : 0.f; }
        __syncthreads();

        const float leftover = sc[0];
        const float nsum = sc[1];
        const bool hasnom = (sc[2] != 0.f);
        const bool done = (sc[4] != 0.f);
        const bool upd = (!done) && hasnom;
        const float denom = (nsum == 0.f) ? 1.f : nsum;

        int po = 0;
        for (int n = tid; n < NS; n += 256) {
            float w = w_s[n];
            int nm = (w != UBv) && m_s[n];
            float gift = (leftover * (nm ? w : 0.f)) / denom;
            float w1 = upd ? (w + gift) : w;
            if (w1 > UBv) po = 1;
            w_s[n] = w1;
            if (upd) a_s[n] = w1;
        }
        ri[tid] = po;
        __syncthreads();
        for (int s = 128; s > 0; s >>= 1) { if (tid < s) ri[tid] |= ri[tid + s]; __syncthreads(); }
        const bool over = (ri[0] != 0);
        __syncthreads();

        if (upd && over)
            for (int n = tid; n < NS; n += 256)
                w_s[n] = fminf(fmaxf(w_s[n], 0.f), UBv);
        if (tid == 0) {
            bool d = done || ((!done) && (!hasnom)) || (upd && (!over));
            sc[4] = d ? 1.f : 0.f;
        }
        __syncthreads();
    }

    for (int n = tid; n < NS; n += 256)
        out[(long long)b * NS + n] = w_s[n];
}

// ============================================================================
extern "C" void kernel_launch(void* const* d_in, const int* in_sizes, int n_in,
                              void* d_out, int out_size)
{
    (void)in_sizes; (void)n_in; (void)out_size;
    const float* x    = (const float*)d_in[0];
    const float* Wih0 = (const float*)d_in[1];
    const float* Whh0 = (const float*)d_in[2];
    const float* bih0 = (const float*)d_in[3];
    const float* bhh0 = (const float*)d_in[4];
    const float* Wih1 = (const float*)d_in[5];
    const float* Whh1 = (const float*)d_in[6];
    const float* bih1 = (const float*)d_in[7];
    const float* bhh1 = (const float*)d_in[8];
    const float* Wa   = (const float*)d_in[9];
    const float* ba   = (const float*)d_in[10];
    const float* Wf   = (const float*)d_in[11];
    const float* bf   = (const float*)d_in[12];
    float* out = (float*)d_out;

    float *xg, *hbuf, *attb, *logb;
    uint4 *a0, *a1, *w0, *w1;
    cudaGetSymbolAddress((void**)&xg,   g_xg);
    cudaGetSymbolAddress((void**)&hbuf, g_hbuf);
    cudaGetSymbolAddress((void**)&attb, g_att);
    cudaGetSymbolAddress((void**)&logb, g_log);
    cudaGetSymbolAddress((void**)&a0, g_a0);
    cudaGetSymbolAddress((void**)&a1, g_a1);
    cudaGetSymbolAddress((void**)&w0, g_w0);
    cudaGetSymbolAddress((void**)&w1, g_w1);

    float* h0p  = hbuf;                          // [2][256][256]
    float* h1p  = hbuf + 2 * B_ * H_;            // [2][256][256]
    float* hfin = hbuf + 4 * B_ * H_;            // [256][256]

    cudaFuncSetAttribute(gru_fused_kernel,
                         cudaFuncAttributeMaxDynamicSharedMemorySize, SCF_SMEM);
    cudaFuncSetAttribute(tc_gemm_kernel,
                         cudaFuncAttributeMaxDynamicSharedMemorySize, TC_SMEM);

    const int M = T_ * B_;   // 64000

    // ---- xg0 = permute(x) @ Wih0^T + bih0  (mma.sync bf16 2-split) ----
    conv_x2_kernel<<<2048, 256>>>(x, a0, a1);
    conv_p2_kernel<<<768, 256>>>(Wih0, w0, w1, (size_t)G3 * 2048 / 8);
    tc_gemm_kernel<<<dim3(G3 / 128, M / 128), 256, TC_SMEM>>>(
        a0, a1, w0, w1, bih0, xg, G3, 2048);

    // ---- fused two-layer scan + xg1 matvec (251 steps, 1 launch) ----
    reset_sync_kernel<<<1, 128>>>();
    gru_fused_kernel<<<128, 384, SCF_SMEM>>>(
        Whh0, bhh0, Wih1, bih1, Whh1, bhh1, xg, h0p, h1p, hfin);

    // heads (fp32 — accuracy-critical, tiny)
    gemm_kernel<<<dim3(NS / BN, B_ / BM), 256>>>(hfin, Wa, ba, attb, B_, NS, H_, 1);
    gemm_kernel<<<dim3(NS / BN, B_ / BM), 256>>>(hfin, Wf, bf, logb, B_, NS, H_, 2);

    finalize_kernel<<<B_, 256>>>(attb, logb, out);
}